// round 1
// baseline (speedup 1.0000x reference)
#include <cuda_runtime.h>
#include <math.h>

#define SEQ     2048
#define DMODEL  2048
#define NHEAD   16
#define HDIM    128
#define FFDIM   8192
#define NTOK    4096      // B*S = 2*2048
#define LN_EPS  1e-5f

// ---------------------------------------------------------------------------
// Scratch (device globals: allocation-free per harness rules)
// ---------------------------------------------------------------------------
__device__ float g_h  [NTOK * DMODEL];       // LN output (reused for LN1 and LN2)
__device__ float g_qkv[NTOK * 3 * DMODEL];   // qkv
__device__ float g_av [NTOK * DMODEL];       // attention output (already [B,S,D])
__device__ float g_x1 [NTOK * DMODEL];       // x after attention residual
__device__ float g_ffn[NTOK * FFDIM];        // gelu(h@w1+b1)

// ---------------------------------------------------------------------------
// LayerNorm: one block per row, 256 threads, float4
// ---------------------------------------------------------------------------
__global__ __launch_bounds__(256) void ln_kernel(
    const float* __restrict__ x, const float* __restrict__ gamma,
    const float* __restrict__ beta, float* __restrict__ out)
{
    int row = blockIdx.x;
    int tid = threadIdx.x;
    const float4* xr = (const float4*)(x + (size_t)row * DMODEL);

    float4 v0 = xr[tid];
    float4 v1 = xr[tid + 256];
    float s  = v0.x + v0.y + v0.z + v0.w + v1.x + v1.y + v1.z + v1.w;
    float sq = v0.x*v0.x + v0.y*v0.y + v0.z*v0.z + v0.w*v0.w
             + v1.x*v1.x + v1.y*v1.y + v1.z*v1.z + v1.w*v1.w;

    // warp reduce
    #pragma unroll
    for (int m = 16; m > 0; m >>= 1) {
        s  += __shfl_xor_sync(0xffffffffu, s,  m);
        sq += __shfl_xor_sync(0xffffffffu, sq, m);
    }
    __shared__ float red_s[8], red_q[8], bc[2];
    int warp = tid >> 5, lane = tid & 31;
    if (lane == 0) { red_s[warp] = s; red_q[warp] = sq; }
    __syncthreads();
    if (tid == 0) {
        float ts = 0.f, tq = 0.f;
        #pragma unroll
        for (int i = 0; i < 8; i++) { ts += red_s[i]; tq += red_q[i]; }
        float mu  = ts * (1.0f / DMODEL);
        float var = tq * (1.0f / DMODEL) - mu * mu;
        bc[0] = mu;
        bc[1] = rsqrtf(var + LN_EPS);
    }
    __syncthreads();
    float mu = bc[0], rinv = bc[1];

    const float4* gv = (const float4*)gamma;
    const float4* bv = (const float4*)beta;
    float4* ov = (float4*)(out + (size_t)row * DMODEL);

    float4 g0 = gv[tid], b0 = bv[tid];
    float4 g1 = gv[tid + 256], b1 = bv[tid + 256];
    float4 o0, o1;
    o0.x = (v0.x - mu) * rinv * g0.x + b0.x;
    o0.y = (v0.y - mu) * rinv * g0.y + b0.y;
    o0.z = (v0.z - mu) * rinv * g0.z + b0.z;
    o0.w = (v0.w - mu) * rinv * g0.w + b0.w;
    o1.x = (v1.x - mu) * rinv * g1.x + b1.x;
    o1.y = (v1.y - mu) * rinv * g1.y + b1.y;
    o1.z = (v1.z - mu) * rinv * g1.z + b1.z;
    o1.w = (v1.w - mu) * rinv * g1.w + b1.w;
    ov[tid]       = o0;
    ov[tid + 256] = o1;
}

// ---------------------------------------------------------------------------
// SGEMM: C[M,N] = A[M,K] @ B[K,N] + bias, epilogue EPI:
//   0 = bias only, 1 = bias + exact GELU, 2 = bias + residual add
// BM=BN=128, BK=8, 256 threads, 8x8 per thread (2x2 of 4-wide frags)
// ---------------------------------------------------------------------------
__device__ __forceinline__ float gelu_exact(float t) {
    return 0.5f * t * (1.0f + erff(t * 0.70710678118654752f));
}

template<int EPI>
__global__ __launch_bounds__(256, 2) void sgemm_kernel(
    const float* __restrict__ A, const float* __restrict__ B,
    const float* __restrict__ bias, const float* __restrict__ res,
    float* __restrict__ C, int M, int N, int K)
{
    __shared__ float As[8][132];   // transposed A tile, padded
    __shared__ float Bs[8][128];

    int tid = threadIdx.x;
    int bx = blockIdx.x;   // N tile
    int by = blockIdx.y;   // M tile
    int tx = tid & 15;
    int ty = tid >> 4;

    // global load indices
    int a_row = (tid >> 1);              // 0..127
    int a_k   = (tid & 1) * 4;           // 0 or 4
    int b_row = (tid >> 5);              // 0..7
    int b_col = (tid & 31) * 4;          // 0..124

    const float* Aptr = A + (size_t)(by * 128 + a_row) * K + a_k;
    const float* Bptr = B + (size_t)b_row * N + bx * 128 + b_col;

    float acc[8][8];
    #pragma unroll
    for (int i = 0; i < 8; i++)
        #pragma unroll
        for (int j = 0; j < 8; j++) acc[i][j] = 0.f;

    int nk = K >> 3;
    float4 a_pre = *(const float4*)Aptr;
    float4 b_pre = *(const float4*)Bptr;

    for (int kb = 0; kb < nk; kb++) {
        As[a_k + 0][a_row] = a_pre.x;
        As[a_k + 1][a_row] = a_pre.y;
        As[a_k + 2][a_row] = a_pre.z;
        As[a_k + 3][a_row] = a_pre.w;
        *(float4*)&Bs[b_row][b_col] = b_pre;
        __syncthreads();

        if (kb + 1 < nk) {
            a_pre = *(const float4*)(Aptr + (kb + 1) * 8);
            b_pre = *(const float4*)(Bptr + (size_t)(kb + 1) * 8 * N);
        }

        #pragma unroll
        for (int k = 0; k < 8; k++) {
            float4 a0 = *(float4*)&As[k][4 * ty];
            float4 a1 = *(float4*)&As[k][64 + 4 * ty];
            float4 b0 = *(float4*)&Bs[k][4 * tx];
            float4 b1 = *(float4*)&Bs[k][64 + 4 * tx];
            float av_[8] = {a0.x, a0.y, a0.z, a0.w, a1.x, a1.y, a1.z, a1.w};
            float bv_[8] = {b0.x, b0.y, b0.z, b0.w, b1.x, b1.y, b1.z, b1.w};
            #pragma unroll
            for (int i = 0; i < 8; i++)
                #pragma unroll
                for (int j = 0; j < 8; j++)
                    acc[i][j] = fmaf(av_[i], bv_[j], acc[i][j]);
        }
        __syncthreads();
    }

    // epilogue
    int gc0 = bx * 128 + 4 * tx;
    int gc1 = gc0 + 64;
    float4 bias0 = *(const float4*)&bias[gc0];
    float4 bias1 = *(const float4*)&bias[gc1];

    #pragma unroll
    for (int ii = 0; ii < 8; ii++) {
        int r = by * 128 + ((ii < 4) ? (4 * ty + ii) : (64 + 4 * ty + ii - 4));
        float4 c0, c1;
        c0.x = acc[ii][0] + bias0.x; c0.y = acc[ii][1] + bias0.y;
        c0.z = acc[ii][2] + bias0.z; c0.w = acc[ii][3] + bias0.w;
        c1.x = acc[ii][4] + bias1.x; c1.y = acc[ii][5] + bias1.y;
        c1.z = acc[ii][6] + bias1.z; c1.w = acc[ii][7] + bias1.w;
        if (EPI == 1) {
            c0.x = gelu_exact(c0.x); c0.y = gelu_exact(c0.y);
            c0.z = gelu_exact(c0.z); c0.w = gelu_exact(c0.w);
            c1.x = gelu_exact(c1.x); c1.y = gelu_exact(c1.y);
            c1.z = gelu_exact(c1.z); c1.w = gelu_exact(c1.w);
        }
        if (EPI == 2) {
            float4 r0 = *(const float4*)&res[(size_t)r * N + gc0];
            float4 r1 = *(const float4*)&res[(size_t)r * N + gc1];
            c0.x += r0.x; c0.y += r0.y; c0.z += r0.z; c0.w += r0.w;
            c1.x += r1.x; c1.y += r1.y; c1.z += r1.z; c1.w += r1.w;
        }
        *(float4*)&C[(size_t)r * N + gc0] = c0;
        *(float4*)&C[(size_t)r * N + gc1] = c1;
    }
}

// ---------------------------------------------------------------------------
// Flash attention, fp32, causal. BM=BN=64, HD=128. One CTA per (q-tile, b*h).
// Thread grid 16x16; S microtile rows {ty+16j}, cols {tx+16i};
// O cols {4tx..4tx+3} and {64+4tx..64+4tx+3}.
// ---------------------------------------------------------------------------
#define QS_STRIDE 132
#define PS_STRIDE 80
#define ATTN_SMEM ((64*QS_STRIDE*2 + 64*128 + 64*PS_STRIDE) * 4)

__global__ __launch_bounds__(256, 1) void attn_kernel(
    const float* __restrict__ qkv, float* __restrict__ av)
{
    extern __shared__ float smem[];
    float* Qs = smem;                       // 64 x 132
    float* Ks = Qs + 64 * QS_STRIDE;        // 64 x 132
    float* Vs = Ks + 64 * QS_STRIDE;        // 64 x 128
    float* Ps = Vs + 64 * 128;              // 64 x 80

    int qt = blockIdx.x;
    int bh = blockIdx.y;
    int b = bh >> 4, h = bh & 15;
    int q0 = qt * 64;
    int tid = threadIdx.x;
    int tx = tid & 15, ty = tid >> 4;

    const float* base = qkv + (size_t)(b * SEQ) * (3 * DMODEL) + h * HDIM;

    // load Q tile [64 x 128]
    #pragma unroll
    for (int it = 0; it < 8; it++) {
        int slot = tid + it * 256;
        int r = slot >> 5, d4 = slot & 31;
        float4 v = *(const float4*)(base + (size_t)(q0 + r) * (3 * DMODEL) + d4 * 4);
        *(float4*)&Qs[r * QS_STRIDE + d4 * 4] = v;
    }

    float m_s[4], l_s[4], O[4][8];
    #pragma unroll
    for (int j = 0; j < 4; j++) {
        m_s[j] = -1e30f; l_s[j] = 0.f;
        #pragma unroll
        for (int i = 0; i < 8; i++) O[j][i] = 0.f;
    }

    const float sc = 0.08838834764831845f;   // 1/sqrt(128)

    for (int kt = 0; kt <= qt; kt++) {
        int k0 = kt * 64;
        __syncthreads();   // prev PV done / Q ready (first iter)
        // load K,V tiles
        #pragma unroll
        for (int it = 0; it < 8; it++) {
            int slot = tid + it * 256;
            int r = slot >> 5, d4 = slot & 31;
            const float* kp = base + DMODEL + (size_t)(k0 + r) * (3 * DMODEL) + d4 * 4;
            *(float4*)&Ks[r * QS_STRIDE + d4 * 4] = *(const float4*)kp;
            *(float4*)&Vs[r * 128 + d4 * 4]       = *(const float4*)(kp + DMODEL);
        }
        __syncthreads();

        // S = Q @ K^T
        float acc[4][4];
        #pragma unroll
        for (int j = 0; j < 4; j++)
            #pragma unroll
            for (int i = 0; i < 4; i++) acc[j][i] = 0.f;

        #pragma unroll 4
        for (int d4 = 0; d4 < 32; d4++) {
            float4 qf[4], kf[4];
            #pragma unroll
            for (int j = 0; j < 4; j++)
                qf[j] = *(float4*)&Qs[(ty + 16 * j) * QS_STRIDE + 4 * d4];
            #pragma unroll
            for (int i = 0; i < 4; i++)
                kf[i] = *(float4*)&Ks[(tx + 16 * i) * QS_STRIDE + 4 * d4];
            #pragma unroll
            for (int j = 0; j < 4; j++)
                #pragma unroll
                for (int i = 0; i < 4; i++) {
                    acc[j][i] = fmaf(qf[j].x, kf[i].x, acc[j][i]);
                    acc[j][i] = fmaf(qf[j].y, kf[i].y, acc[j][i]);
                    acc[j][i] = fmaf(qf[j].z, kf[i].z, acc[j][i]);
                    acc[j][i] = fmaf(qf[j].w, kf[i].w, acc[j][i]);
                }
        }

        bool diag = (kt == qt);
        #pragma unroll
        for (int j = 0; j < 4; j++) {
            int rloc = ty + 16 * j;
            float rmax = -1e30f;
            #pragma unroll
            for (int i = 0; i < 4; i++) {
                float s = acc[j][i] * sc;
                if (diag && (tx + 16 * i) > rloc) s = -1e30f;
                acc[j][i] = s;
                rmax = fmaxf(rmax, s);
            }
            #pragma unroll
            for (int m = 1; m < 16; m <<= 1)
                rmax = fmaxf(rmax, __shfl_xor_sync(0xffffffffu, rmax, m));
            float m_new = fmaxf(m_s[j], rmax);
            float corr = expf(m_s[j] - m_new);
            m_s[j] = m_new;
            float rsum = 0.f;
            #pragma unroll
            for (int i = 0; i < 4; i++) {
                float p = expf(acc[j][i] - m_new);
                acc[j][i] = p;
                rsum += p;
            }
            #pragma unroll
            for (int m = 1; m < 16; m <<= 1)
                rsum += __shfl_xor_sync(0xffffffffu, rsum, m);
            l_s[j] = l_s[j] * corr + rsum;
            #pragma unroll
            for (int i = 0; i < 8; i++) O[j][i] *= corr;
            #pragma unroll
            for (int i = 0; i < 4; i++)
                Ps[rloc * PS_STRIDE + tx + 16 * i] = acc[j][i];
        }
        __syncthreads();

        // O += P @ V
        #pragma unroll 4
        for (int kk = 0; kk < 64; kk++) {
            float pj[4];
            #pragma unroll
            for (int j = 0; j < 4; j++)
                pj[j] = Ps[(ty + 16 * j) * PS_STRIDE + kk];
            float4 v0 = *(float4*)&Vs[kk * 128 + 4 * tx];
            float4 v1 = *(float4*)&Vs[kk * 128 + 64 + 4 * tx];
            #pragma unroll
            for (int j = 0; j < 4; j++) {
                O[j][0] = fmaf(pj[j], v0.x, O[j][0]);
                O[j][1] = fmaf(pj[j], v0.y, O[j][1]);
                O[j][2] = fmaf(pj[j], v0.z, O[j][2]);
                O[j][3] = fmaf(pj[j], v0.w, O[j][3]);
                O[j][4] = fmaf(pj[j], v1.x, O[j][4]);
                O[j][5] = fmaf(pj[j], v1.y, O[j][5]);
                O[j][6] = fmaf(pj[j], v1.z, O[j][6]);
                O[j][7] = fmaf(pj[j], v1.w, O[j][7]);
            }
        }
    }

    // write out: av is [token, D] with head offset h*128
    float* obase = av + (size_t)(b * SEQ + q0) * DMODEL + h * HDIM;
    #pragma unroll
    for (int j = 0; j < 4; j++) {
        float inv = 1.0f / l_s[j];
        float4 o0, o1;
        o0.x = O[j][0] * inv; o0.y = O[j][1] * inv;
        o0.z = O[j][2] * inv; o0.w = O[j][3] * inv;
        o1.x = O[j][4] * inv; o1.y = O[j][5] * inv;
        o1.z = O[j][6] * inv; o1.w = O[j][7] * inv;
        float* orow = obase + (size_t)(ty + 16 * j) * DMODEL;
        *(float4*)&orow[4 * tx]      = o0;
        *(float4*)&orow[64 + 4 * tx] = o1;
    }
}

// ---------------------------------------------------------------------------
// Launch
// ---------------------------------------------------------------------------
extern "C" void kernel_launch(void* const* d_in, const int* in_sizes, int n_in,
                              void* d_out, int out_size)
{
    const float* x     = (const float*)d_in[0];
    const float* ln1_g = (const float*)d_in[1];
    const float* ln1_b = (const float*)d_in[2];
    const float* qkv_w = (const float*)d_in[3];
    const float* qkv_b = (const float*)d_in[4];
    const float* out_w = (const float*)d_in[5];
    const float* out_b = (const float*)d_in[6];
    const float* ln2_g = (const float*)d_in[7];
    const float* ln2_b = (const float*)d_in[8];
    const float* w1    = (const float*)d_in[9];
    const float* b1    = (const float*)d_in[10];
    const float* w2    = (const float*)d_in[11];
    const float* b2    = (const float*)d_in[12];
    float* out = (float*)d_out;

    float *h_p, *qkv_p, *av_p, *x1_p, *ffn_p;
    cudaGetSymbolAddress((void**)&h_p,   g_h);
    cudaGetSymbolAddress((void**)&qkv_p, g_qkv);
    cudaGetSymbolAddress((void**)&av_p,  g_av);
    cudaGetSymbolAddress((void**)&x1_p,  g_x1);
    cudaGetSymbolAddress((void**)&ffn_p, g_ffn);

    // 1. LN1
    ln_kernel<<<NTOK, 256>>>(x, ln1_g, ln1_b, h_p);

    // 2. QKV = LN1(x) @ qkv_w + qkv_b
    sgemm_kernel<0><<<dim3(3 * DMODEL / 128, NTOK / 128), 256>>>(
        h_p, qkv_w, qkv_b, nullptr, qkv_p, NTOK, 3 * DMODEL, DMODEL);

    // 3. flash attention
    cudaFuncSetAttribute(attn_kernel, cudaFuncAttributeMaxDynamicSharedMemorySize,
                         ATTN_SMEM);
    attn_kernel<<<dim3(SEQ / 64, 2 * NHEAD), 256, ATTN_SMEM>>>(qkv_p, av_p);

    // 4. x1 = x + av @ out_w + out_b
    sgemm_kernel<2><<<dim3(DMODEL / 128, NTOK / 128), 256>>>(
        av_p, out_w, out_b, x, x1_p, NTOK, DMODEL, DMODEL);

    // 5. LN2
    ln_kernel<<<NTOK, 256>>>(x1_p, ln2_g, ln2_b, h_p);

    // 6. ffn = gelu(LN2(x1) @ w1 + b1)
    sgemm_kernel<1><<<dim3(FFDIM / 128, NTOK / 128), 256>>>(
        h_p, w1, b1, nullptr, ffn_p, NTOK, FFDIM, DMODEL);

    // 7. out = x1 + ffn @ w2 + b2
    sgemm_kernel<2><<<dim3(DMODEL / 128, NTOK / 128), 256>>>(
        ffn_p, w2, b2, x1_p, out, NTOK, DMODEL, FFDIM);
}

// round 2
// speedup vs baseline: 1.6496x; 1.6496x over previous
#include <cuda_runtime.h>
#include <math.h>

#define SEQ     2048
#define DMODEL  2048
#define NHEAD   16
#define HDIM    128
#define FFDIM   8192
#define NTOK    4096      // B*S = 2*2048
#define LN_EPS  1e-5f

// ---------------------------------------------------------------------------
// Scratch (device globals: allocation-free per harness rules)
// ---------------------------------------------------------------------------
__device__ float g_h  [NTOK * DMODEL];       // LN output (reused for LN1 and LN2)
__device__ float g_qkv[NTOK * 3 * DMODEL];   // qkv
__device__ float g_av [NTOK * DMODEL];       // attention output (already [B,S,D])
__device__ float g_x1 [NTOK * DMODEL];       // x after attention residual
__device__ float g_ffn[NTOK * FFDIM];        // gelu(h@w1+b1)

// ---------------------------------------------------------------------------
// LayerNorm: one block per row, 256 threads, float4
// ---------------------------------------------------------------------------
__global__ __launch_bounds__(256) void ln_kernel(
    const float* __restrict__ x, const float* __restrict__ gamma,
    const float* __restrict__ beta, float* __restrict__ out)
{
    int row = blockIdx.x;
    int tid = threadIdx.x;
    const float4* xr = (const float4*)(x + (size_t)row * DMODEL);

    float4 v0 = xr[tid];
    float4 v1 = xr[tid + 256];
    float s  = v0.x + v0.y + v0.z + v0.w + v1.x + v1.y + v1.z + v1.w;
    float sq = v0.x*v0.x + v0.y*v0.y + v0.z*v0.z + v0.w*v0.w
             + v1.x*v1.x + v1.y*v1.y + v1.z*v1.z + v1.w*v1.w;

    // warp reduce
    #pragma unroll
    for (int m = 16; m > 0; m >>= 1) {
        s  += __shfl_xor_sync(0xffffffffu, s,  m);
        sq += __shfl_xor_sync(0xffffffffu, sq, m);
    }
    __shared__ float red_s[8], red_q[8], bc[2];
    int warp = tid >> 5, lane = tid & 31;
    if (lane == 0) { red_s[warp] = s; red_q[warp] = sq; }
    __syncthreads();
    if (tid == 0) {
        float ts = 0.f, tq = 0.f;
        #pragma unroll
        for (int i = 0; i < 8; i++) { ts += red_s[i]; tq += red_q[i]; }
        float mu  = ts * (1.0f / DMODEL);
        float var = tq * (1.0f / DMODEL) - mu * mu;
        bc[0] = mu;
        bc[1] = rsqrtf(var + LN_EPS);
    }
    __syncthreads();
    float mu = bc[0], rinv = bc[1];

    const float4* gv = (const float4*)gamma;
    const float4* bv = (const float4*)beta;
    float4* ov = (float4*)(out + (size_t)row * DMODEL);

    float4 g0 = gv[tid], b0 = bv[tid];
    float4 g1 = gv[tid + 256], b1 = bv[tid + 256];
    float4 o0, o1;
    o0.x = (v0.x - mu) * rinv * g0.x + b0.x;
    o0.y = (v0.y - mu) * rinv * g0.y + b0.y;
    o0.z = (v0.z - mu) * rinv * g0.z + b0.z;
    o0.w = (v0.w - mu) * rinv * g0.w + b0.w;
    o1.x = (v1.x - mu) * rinv * g1.x + b1.x;
    o1.y = (v1.y - mu) * rinv * g1.y + b1.y;
    o1.z = (v1.z - mu) * rinv * g1.z + b1.z;
    o1.w = (v1.w - mu) * rinv * g1.w + b1.w;
    ov[tid]       = o0;
    ov[tid + 256] = o1;
}

// ---------------------------------------------------------------------------
// SGEMM: C[M,N] = A[M,K] @ B[K,N] + bias, epilogue EPI:
//   0 = bias only, 1 = bias + exact GELU, 2 = bias + residual add
// BM=BN=128, BK=8, 256 threads, 8x8 per thread (2x2 of 4-wide frags)
// ---------------------------------------------------------------------------
__device__ __forceinline__ float gelu_exact(float t) {
    return 0.5f * t * (1.0f + erff(t * 0.70710678118654752f));
}

template<int EPI>
__global__ __launch_bounds__(256, 2) void sgemm_kernel(
    const float* __restrict__ A, const float* __restrict__ B,
    const float* __restrict__ bias, const float* __restrict__ res,
    float* __restrict__ C, int M, int N, int K)
{
    __shared__ float As[8][132];   // transposed A tile, padded
    __shared__ float Bs[8][128];

    int tid = threadIdx.x;
    int bx = blockIdx.x;   // N tile
    int by = blockIdx.y;   // M tile
    int tx = tid & 15;
    int ty = tid >> 4;

    // global load indices
    int a_row = (tid >> 1);              // 0..127
    int a_k   = (tid & 1) * 4;           // 0 or 4
    int b_row = (tid >> 5);              // 0..7
    int b_col = (tid & 31) * 4;          // 0..124

    const float* Aptr = A + (size_t)(by * 128 + a_row) * K + a_k;
    const float* Bptr = B + (size_t)b_row * N + bx * 128 + b_col;

    float acc[8][8];
    #pragma unroll
    for (int i = 0; i < 8; i++)
        #pragma unroll
        for (int j = 0; j < 8; j++) acc[i][j] = 0.f;

    int nk = K >> 3;
    float4 a_pre = *(const float4*)Aptr;
    float4 b_pre = *(const float4*)Bptr;

    for (int kb = 0; kb < nk; kb++) {
        As[a_k + 0][a_row] = a_pre.x;
        As[a_k + 1][a_row] = a_pre.y;
        As[a_k + 2][a_row] = a_pre.z;
        As[a_k + 3][a_row] = a_pre.w;
        *(float4*)&Bs[b_row][b_col] = b_pre;
        __syncthreads();

        if (kb + 1 < nk) {
            a_pre = *(const float4*)(Aptr + (kb + 1) * 8);
            b_pre = *(const float4*)(Bptr + (size_t)(kb + 1) * 8 * N);
        }

        #pragma unroll
        for (int k = 0; k < 8; k++) {
            float4 a0 = *(float4*)&As[k][4 * ty];
            float4 a1 = *(float4*)&As[k][64 + 4 * ty];
            float4 b0 = *(float4*)&Bs[k][4 * tx];
            float4 b1 = *(float4*)&Bs[k][64 + 4 * tx];
            float av_[8] = {a0.x, a0.y, a0.z, a0.w, a1.x, a1.y, a1.z, a1.w};
            float bv_[8] = {b0.x, b0.y, b0.z, b0.w, b1.x, b1.y, b1.z, b1.w};
            #pragma unroll
            for (int i = 0; i < 8; i++)
                #pragma unroll
                for (int j = 0; j < 8; j++)
                    acc[i][j] = fmaf(av_[i], bv_[j], acc[i][j]);
        }
        __syncthreads();
    }

    // epilogue
    int gc0 = bx * 128 + 4 * tx;
    int gc1 = gc0 + 64;
    float4 bias0 = *(const float4*)&bias[gc0];
    float4 bias1 = *(const float4*)&bias[gc1];

    #pragma unroll
    for (int ii = 0; ii < 8; ii++) {
        int r = by * 128 + ((ii < 4) ? (4 * ty + ii) : (64 + 4 * ty + ii - 4));
        float4 c0, c1;
        c0.x = acc[ii][0] + bias0.x; c0.y = acc[ii][1] + bias0.y;
        c0.z = acc[ii][2] + bias0.z; c0.w = acc[ii][3] + bias0.w;
        c1.x = acc[ii][4] + bias1.x; c1.y = acc[ii][5] + bias1.y;
        c1.z = acc[ii][6] + bias1.z; c1.w = acc[ii][7] + bias1.w;
        if (EPI == 1) {
            c0.x = gelu_exact(c0.x); c0.y = gelu_exact(c0.y);
            c0.z = gelu_exact(c0.z); c0.w = gelu_exact(c0.w);
            c1.x = gelu_exact(c1.x); c1.y = gelu_exact(c1.y);
            c1.z = gelu_exact(c1.z); c1.w = gelu_exact(c1.w);
        }
        if (EPI == 2) {
            float4 r0 = *(const float4*)&res[(size_t)r * N + gc0];
            float4 r1 = *(const float4*)&res[(size_t)r * N + gc1];
            c0.x += r0.x; c0.y += r0.y; c0.z += r0.z; c0.w += r0.w;
            c1.x += r1.x; c1.y += r1.y; c1.z += r1.z; c1.w += r1.w;
        }
        *(float4*)&C[(size_t)r * N + gc0] = c0;
        *(float4*)&C[(size_t)r * N + gc1] = c1;
    }
}

// ---------------------------------------------------------------------------
// Flash attention, fp32, causal. BM=BN=64, HD=128. One CTA per (q-tile, b*h).
// Thread grid 16x16; S microtile rows {ty+16j}, cols {tx+16i};
// O cols {4tx..4tx+3} and {64+4tx..64+4tx+3}.
// ---------------------------------------------------------------------------
#define QS_STRIDE 132
#define PS_STRIDE 80
#define ATTN_SMEM ((64*QS_STRIDE*2 + 64*128 + 64*PS_STRIDE) * 4)

__global__ __launch_bounds__(256, 1) void attn_kernel(
    const float* __restrict__ qkv, float* __restrict__ av)
{
    extern __shared__ float smem[];
    float* Qs = smem;                       // 64 x 132
    float* Ks = Qs + 64 * QS_STRIDE;        // 64 x 132
    float* Vs = Ks + 64 * QS_STRIDE;        // 64 x 128
    float* Ps = Vs + 64 * 128;              // 64 x 80

    int qt = blockIdx.x;
    int bh = blockIdx.y;
    int b = bh >> 4, h = bh & 15;
    int q0 = qt * 64;
    int tid = threadIdx.x;
    int tx = tid & 15, ty = tid >> 4;

    const float* base = qkv + (size_t)(b * SEQ) * (3 * DMODEL) + h * HDIM;

    // load Q tile [64 x 128]
    #pragma unroll
    for (int it = 0; it < 8; it++) {
        int slot = tid + it * 256;
        int r = slot >> 5, d4 = slot & 31;
        float4 v = *(const float4*)(base + (size_t)(q0 + r) * (3 * DMODEL) + d4 * 4);
        *(float4*)&Qs[r * QS_STRIDE + d4 * 4] = v;
    }

    float m_s[4], l_s[4], O[4][8];
    #pragma unroll
    for (int j = 0; j < 4; j++) {
        m_s[j] = -1e30f; l_s[j] = 0.f;
        #pragma unroll
        for (int i = 0; i < 8; i++) O[j][i] = 0.f;
    }

    const float sc = 0.08838834764831845f;   // 1/sqrt(128)

    for (int kt = 0; kt <= qt; kt++) {
        int k0 = kt * 64;
        __syncthreads();   // prev PV done / Q ready (first iter)
        // load K,V tiles
        #pragma unroll
        for (int it = 0; it < 8; it++) {
            int slot = tid + it * 256;
            int r = slot >> 5, d4 = slot & 31;
            const float* kp = base + DMODEL + (size_t)(k0 + r) * (3 * DMODEL) + d4 * 4;
            *(float4*)&Ks[r * QS_STRIDE + d4 * 4] = *(const float4*)kp;
            *(float4*)&Vs[r * 128 + d4 * 4]       = *(const float4*)(kp + DMODEL);
        }
        __syncthreads();

        // S = Q @ K^T
        float acc[4][4];
        #pragma unroll
        for (int j = 0; j < 4; j++)
            #pragma unroll
            for (int i = 0; i < 4; i++) acc[j][i] = 0.f;

        #pragma unroll 4
        for (int d4 = 0; d4 < 32; d4++) {
            float4 qf[4], kf[4];
            #pragma unroll
            for (int j = 0; j < 4; j++)
                qf[j] = *(float4*)&Qs[(ty + 16 * j) * QS_STRIDE + 4 * d4];
            #pragma unroll
            for (int i = 0; i < 4; i++)
                kf[i] = *(float4*)&Ks[(tx + 16 * i) * QS_STRIDE + 4 * d4];
            #pragma unroll
            for (int j = 0; j < 4; j++)
                #pragma unroll
                for (int i = 0; i < 4; i++) {
                    acc[j][i] = fmaf(qf[j].x, kf[i].x, acc[j][i]);
                    acc[j][i] = fmaf(qf[j].y, kf[i].y, acc[j][i]);
                    acc[j][i] = fmaf(qf[j].z, kf[i].z, acc[j][i]);
                    acc[j][i] = fmaf(qf[j].w, kf[i].w, acc[j][i]);
                }
        }

        bool diag = (kt == qt);
        #pragma unroll
        for (int j = 0; j < 4; j++) {
            int rloc = ty + 16 * j;
            float rmax = -1e30f;
            #pragma unroll
            for (int i = 0; i < 4; i++) {
                float s = acc[j][i] * sc;
                if (diag && (tx + 16 * i) > rloc) s = -1e30f;
                acc[j][i] = s;
                rmax = fmaxf(rmax, s);
            }
            #pragma unroll
            for (int m = 1; m < 16; m <<= 1)
                rmax = fmaxf(rmax, __shfl_xor_sync(0xffffffffu, rmax, m));
            float m_new = fmaxf(m_s[j], rmax);
            float corr = expf(m_s[j] - m_new);
            m_s[j] = m_new;
            float rsum = 0.f;
            #pragma unroll
            for (int i = 0; i < 4; i++) {
                float p = expf(acc[j][i] - m_new);
                acc[j][i] = p;
                rsum += p;
            }
            #pragma unroll
            for (int m = 1; m < 16; m <<= 1)
                rsum += __shfl_xor_sync(0xffffffffu, rsum, m);
            l_s[j] = l_s[j] * corr + rsum;
            #pragma unroll
            for (int i = 0; i < 8; i++) O[j][i] *= corr;
            #pragma unroll
            for (int i = 0; i < 4; i++)
                Ps[rloc * PS_STRIDE + tx + 16 * i] = acc[j][i];
        }
        __syncthreads();

        // O += P @ V
        #pragma unroll 4
        for (int kk = 0; kk < 64; kk++) {
            float pj[4];
            #pragma unroll
            for (int j = 0; j < 4; j++)
                pj[j] = Ps[(ty + 16 * j) * PS_STRIDE + kk];
            float4 v0 = *(float4*)&Vs[kk * 128 + 4 * tx];
            float4 v1 = *(float4*)&Vs[kk * 128 + 64 + 4 * tx];
            #pragma unroll
            for (int j = 0; j < 4; j++) {
                O[j][0] = fmaf(pj[j], v0.x, O[j][0]);
                O[j][1] = fmaf(pj[j], v0.y, O[j][1]);
                O[j][2] = fmaf(pj[j], v0.z, O[j][2]);
                O[j][3] = fmaf(pj[j], v0.w, O[j][3]);
                O[j][4] = fmaf(pj[j], v1.x, O[j][4]);
                O[j][5] = fmaf(pj[j], v1.y, O[j][5]);
                O[j][6] = fmaf(pj[j], v1.z, O[j][6]);
                O[j][7] = fmaf(pj[j], v1.w, O[j][7]);
            }
        }
    }

    // write out: av is [token, D] with head offset h*128
    float* obase = av + (size_t)(b * SEQ + q0) * DMODEL + h * HDIM;
    #pragma unroll
    for (int j = 0; j < 4; j++) {
        float inv = 1.0f / l_s[j];
        float4 o0, o1;
        o0.x = O[j][0] * inv; o0.y = O[j][1] * inv;
        o0.z = O[j][2] * inv; o0.w = O[j][3] * inv;
        o1.x = O[j][4] * inv; o1.y = O[j][5] * inv;
        o1.z = O[j][6] * inv; o1.w = O[j][7] * inv;
        float* orow = obase + (size_t)(ty + 16 * j) * DMODEL;
        *(float4*)&orow[4 * tx]      = o0;
        *(float4*)&orow[64 + 4 * tx] = o1;
    }
}

// ---------------------------------------------------------------------------
// Launch
// ---------------------------------------------------------------------------
extern "C" void kernel_launch(void* const* d_in, const int* in_sizes, int n_in,
                              void* d_out, int out_size)
{
    const float* x     = (const float*)d_in[0];
    const float* ln1_g = (const float*)d_in[1];
    const float* ln1_b = (const float*)d_in[2];
    const float* qkv_w = (const float*)d_in[3];
    const float* qkv_b = (const float*)d_in[4];
    const float* out_w = (const float*)d_in[5];
    const float* out_b = (const float*)d_in[6];
    const float* ln2_g = (const float*)d_in[7];
    const float* ln2_b = (const float*)d_in[8];
    const float* w1    = (const float*)d_in[9];
    const float* b1    = (const float*)d_in[10];
    const float* w2    = (const float*)d_in[11];
    const float* b2    = (const float*)d_in[12];
    float* out = (float*)d_out;

    float *h_p, *qkv_p, *av_p, *x1_p, *ffn_p;
    cudaGetSymbolAddress((void**)&h_p,   g_h);
    cudaGetSymbolAddress((void**)&qkv_p, g_qkv);
    cudaGetSymbolAddress((void**)&av_p,  g_av);
    cudaGetSymbolAddress((void**)&x1_p,  g_x1);
    cudaGetSymbolAddress((void**)&ffn_p, g_ffn);

    // 1. LN1
    ln_kernel<<<NTOK, 256>>>(x, ln1_g, ln1_b, h_p);

    // 2. QKV = LN1(x) @ qkv_w + qkv_b
    sgemm_kernel<0><<<dim3(3 * DMODEL / 128, NTOK / 128), 256>>>(
        h_p, qkv_w, qkv_b, nullptr, qkv_p, NTOK, 3 * DMODEL, DMODEL);

    // 3. flash attention
    cudaFuncSetAttribute(attn_kernel, cudaFuncAttributeMaxDynamicSharedMemorySize,
                         ATTN_SMEM);
    attn_kernel<<<dim3(SEQ / 64, 2 * NHEAD), 256, ATTN_SMEM>>>(qkv_p, av_p);

    // 4. x1 = x + av @ out_w + out_b
    sgemm_kernel<2><<<dim3(DMODEL / 128, NTOK / 128), 256>>>(
        av_p, out_w, out_b, x, x1_p, NTOK, DMODEL, DMODEL);

    // 5. LN2
    ln_kernel<<<NTOK, 256>>>(x1_p, ln2_g, ln2_b, h_p);

    // 6. ffn = gelu(LN2(x1) @ w1 + b1)
    sgemm_kernel<1><<<dim3(FFDIM / 128, NTOK / 128), 256>>>(
        h_p, w1, b1, nullptr, ffn_p, NTOK, FFDIM, DMODEL);

    // 7. out = x1 + ffn @ w2 + b2
    sgemm_kernel<2><<<dim3(DMODEL / 128, NTOK / 128), 256>>>(
        ffn_p, w2, b2, x1_p, out, NTOK, DMODEL, FFDIM);
}

// round 4
// speedup vs baseline: 3.6630x; 2.2206x over previous
#include <cuda_runtime.h>
#include <math.h>
#include <stdint.h>

#define SEQ     2048
#define DMODEL  2048
#define NHEAD   16
#define FFDIM   8192
#define NTOK    4096
#define LN_EPS  1e-5f

__device__ float g_h  [(size_t)NTOK * DMODEL];
__device__ float g_qkv[(size_t)NTOK * 3 * DMODEL];
__device__ float g_av [(size_t)NTOK * DMODEL];
__device__ float g_x1 [(size_t)NTOK * DMODEL];
__device__ float g_ffn[(size_t)NTOK * FFDIM];
__device__ float g_wqkv_r[(size_t)3 * DMODEL * DMODEL];
__device__ float g_wout_r[(size_t)DMODEL * DMODEL];
__device__ float g_w1_r  [(size_t)DMODEL * FFDIM];
__device__ float g_w2_r  [(size_t)FFDIM * DMODEL];

// ---------------- helpers ----------------
__device__ __forceinline__ float tf32r(float x){
  uint32_t u; asm("cvt.rna.tf32.f32 %0, %1;" : "=r"(u) : "f"(x));
  return __uint_as_float(u);
}
__device__ __forceinline__ uint32_t s2u(const void* p){
  uint32_t a;
  asm("{ .reg .u64 t; cvta.to.shared.u64 t, %1; cvt.u32.u64 %0, t; }" : "=r"(a) : "l"(p));
  return a;
}
__device__ __forceinline__ void cpa16(uint32_t dst, const void* src){
  asm volatile("cp.async.cg.shared.global [%0], [%1], 16;" :: "r"(dst), "l"(src));
}
__device__ __forceinline__ void cp_commit(){ asm volatile("cp.async.commit_group;"); }
__device__ __forceinline__ void cp_wait0(){ asm volatile("cp.async.wait_group 0;" ::: "memory"); }
__device__ __forceinline__ void mma8(float* c, const uint32_t* a, const uint32_t* b){
  asm volatile("mma.sync.aligned.m16n8k8.row.col.f32.tf32.tf32.f32 "
    "{%0,%1,%2,%3}, {%4,%5,%6,%7}, {%8,%9}, {%0,%1,%2,%3};"
    : "+f"(c[0]), "+f"(c[1]), "+f"(c[2]), "+f"(c[3])
    : "r"(a[0]), "r"(a[1]), "r"(a[2]), "r"(a[3]), "r"(b[0]), "r"(b[1]));
}
__device__ __forceinline__ float gelu_exact(float t){
  return 0.5f * t * (1.0f + erff(t * 0.70710678118654752f));
}

// ---- elementwise tf32 round (weights) ----
__global__ __launch_bounds__(256) void round_kernel(
    const float* __restrict__ in, float* __restrict__ out)
{
  size_t i = (size_t)blockIdx.x * 256 + threadIdx.x;
  float4 v = ((const float4*)in)[i];
  v.x = tf32r(v.x); v.y = tf32r(v.y); v.z = tf32r(v.z); v.w = tf32r(v.w);
  ((float4*)out)[i] = v;
}

// ---- LayerNorm -> row-major tf32-rounded ----
__global__ __launch_bounds__(256) void ln_kernel(
    const float* __restrict__ x, const float* __restrict__ gamma,
    const float* __restrict__ beta, float* __restrict__ out)
{
  int row = blockIdx.x;
  int tid = threadIdx.x;
  const float4* xr = (const float4*)(x + (size_t)row * DMODEL);
  float4 v0 = xr[tid];
  float4 v1 = xr[tid + 256];
  float s  = v0.x + v0.y + v0.z + v0.w + v1.x + v1.y + v1.z + v1.w;
  float sq = v0.x*v0.x + v0.y*v0.y + v0.z*v0.z + v0.w*v0.w
           + v1.x*v1.x + v1.y*v1.y + v1.z*v1.z + v1.w*v1.w;
  #pragma unroll
  for (int m = 16; m > 0; m >>= 1){
    s  += __shfl_xor_sync(0xffffffffu, s,  m);
    sq += __shfl_xor_sync(0xffffffffu, sq, m);
  }
  __shared__ float red_s[8], red_q[8], bc[2];
  int warp = tid >> 5, lane = tid & 31;
  if (lane == 0){ red_s[warp] = s; red_q[warp] = sq; }
  __syncthreads();
  if (tid == 0){
    float ts = 0.f, tq = 0.f;
    #pragma unroll
    for (int i = 0; i < 8; i++){ ts += red_s[i]; tq += red_q[i]; }
    float mu  = ts * (1.0f / DMODEL);
    float var = tq * (1.0f / DMODEL) - mu * mu;
    bc[0] = mu; bc[1] = rsqrtf(var + LN_EPS);
  }
  __syncthreads();
  float mu = bc[0], rinv = bc[1];
  const float4* gv = (const float4*)gamma;
  const float4* bv = (const float4*)beta;
  float4 g0 = gv[tid], b0 = bv[tid];
  float4 g1 = gv[tid + 256], b1 = bv[tid + 256];
  float4 o0, o1;
  o0.x = tf32r((v0.x - mu) * rinv * g0.x + b0.x);
  o0.y = tf32r((v0.y - mu) * rinv * g0.y + b0.y);
  o0.z = tf32r((v0.z - mu) * rinv * g0.z + b0.z);
  o0.w = tf32r((v0.w - mu) * rinv * g0.w + b0.w);
  o1.x = tf32r((v1.x - mu) * rinv * g1.x + b1.x);
  o1.y = tf32r((v1.y - mu) * rinv * g1.y + b1.y);
  o1.z = tf32r((v1.z - mu) * rinv * g1.z + b1.z);
  o1.w = tf32r((v1.w - mu) * rinv * g1.w + b1.w);
  float4* ov = (float4*)(out + (size_t)row * DMODEL);
  ov[tid]       = o0;
  ov[tid + 256] = o1;
}

// ---------------------------------------------------------------------------
// tf32 mma.sync GEMM. C[M,N] = A[M,K] @ B[K,N] (+bias, epilogue).
// A,B row-major, already tf32-rounded. BM=BN=128, BK=16, 256 thr, 8 warps 2x4,
// warp tile 64x32 (4 m16 x 4 n8 mma tiles). cp.async double buffered.
// EPI: 0=bias, 1=bias+gelu, 2=bias+residual.  ROUT: round outputs to tf32.
// ---------------------------------------------------------------------------
template<int EPI, int ROUT>
__global__ __launch_bounds__(256, 2) void tfgemm(
    const float* __restrict__ A, const float* __restrict__ B,
    const float* __restrict__ bias, const float* __restrict__ res,
    float* __restrict__ C, int M, int N, int K)
{
  __shared__ float As[2][128][20];
  __shared__ float Bs[2][16][136];

  int tid = threadIdx.x, lane = tid & 31, warp = tid >> 5;
  int bx = blockIdx.x, by = blockIdx.y;
  int wm = (warp >> 2) * 64, wn = (warp & 3) * 32;
  int gid = lane >> 2, tig = lane & 3;

  // A load mapping: chunk c = tid + 256*i -> row = c>>2, k4 = (c&3)*4
  int a_r0 = tid >> 2;             // rows 0..63 (i=0), +64 (i=1)
  int a_k4 = (tid & 3) * 4;
  // B load mapping: chunk c = tid + 256*i -> k = c>>5, n4 = (c&31)*4
  int b_k0 = tid >> 5;             // 0..7 (i=0), +8 (i=1)
  int b_n4 = (tid & 31) * 4;

  const float* Ag = A + (size_t)(by * 128 + a_r0) * K + a_k4;
  const float* Bg = B + (size_t)b_k0 * N + bx * 128 + b_n4;

  uint32_t as_d0 = s2u(&As[0][a_r0][a_k4]);
  uint32_t as_d1 = s2u(&As[0][a_r0 + 64][a_k4]);
  uint32_t bs_d0 = s2u(&Bs[0][b_k0][b_n4]);
  uint32_t bs_d1 = s2u(&Bs[0][b_k0 + 8][b_n4]);
  const uint32_t aSt = sizeof(float) * 128 * 20;
  const uint32_t bSt = sizeof(float) * 16 * 136;

  float c[4][4][4];
  #pragma unroll
  for (int mi = 0; mi < 4; mi++)
    #pragma unroll
    for (int ni = 0; ni < 4; ni++)
      #pragma unroll
      for (int q = 0; q < 4; q++) c[mi][ni][q] = 0.f;

  int nk = K >> 4;
  // prefetch tile 0 into stage 0
  cpa16(as_d0, Ag);
  cpa16(as_d1, Ag + (size_t)64 * K);
  cpa16(bs_d0, Bg);
  cpa16(bs_d1, Bg + (size_t)8 * N);
  cp_commit();

  int st = 0;
  for (int kb = 0; kb < nk; kb++){
    cp_wait0();
    __syncthreads();
    if (kb + 1 < nk){
      const float* Agn = Ag + (kb + 1) * 16;
      const float* Bgn = Bg + (size_t)(kb + 1) * 16 * N;
      uint32_t so = (st ^ 1) ? aSt : 0;
      uint32_t sb = (st ^ 1) ? bSt : 0;
      cpa16(as_d0 + so, Agn);
      cpa16(as_d1 + so, Agn + (size_t)64 * K);
      cpa16(bs_d0 + sb, Bgn);
      cpa16(bs_d1 + sb, Bgn + (size_t)8 * N);
      cp_commit();
    }
    #pragma unroll
    for (int ks = 0; ks < 2; ks++){
      int k0 = ks * 8;
      uint32_t a[4][4], b[4][2];
      #pragma unroll
      for (int mi = 0; mi < 4; mi++){
        int r0 = wm + mi * 16 + gid;
        a[mi][0] = __float_as_uint(As[st][r0][k0 + tig]);
        a[mi][1] = __float_as_uint(As[st][r0 + 8][k0 + tig]);
        a[mi][2] = __float_as_uint(As[st][r0][k0 + tig + 4]);
        a[mi][3] = __float_as_uint(As[st][r0 + 8][k0 + tig + 4]);
      }
      #pragma unroll
      for (int ni = 0; ni < 4; ni++){
        int n0 = wn + ni * 8 + gid;
        b[ni][0] = __float_as_uint(Bs[st][k0 + tig][n0]);
        b[ni][1] = __float_as_uint(Bs[st][k0 + tig + 4][n0]);
      }
      #pragma unroll
      for (int mi = 0; mi < 4; mi++)
        #pragma unroll
        for (int ni = 0; ni < 4; ni++)
          mma8(c[mi][ni], a[mi], b[ni]);
    }
    st ^= 1;
    __syncthreads();
  }

  // epilogue
  #pragma unroll
  for (int ni = 0; ni < 4; ni++){
    int col = bx * 128 + wn + ni * 8 + 2 * tig;
    float bb0 = bias[col], bb1 = bias[col + 1];
    #pragma unroll
    for (int mi = 0; mi < 4; mi++){
      int row0 = by * 128 + wm + mi * 16 + gid;
      float2 v0, v1;
      v0.x = c[mi][ni][0] + bb0; v0.y = c[mi][ni][1] + bb1;
      v1.x = c[mi][ni][2] + bb0; v1.y = c[mi][ni][3] + bb1;
      if (EPI == 1){
        v0.x = gelu_exact(v0.x); v0.y = gelu_exact(v0.y);
        v1.x = gelu_exact(v1.x); v1.y = gelu_exact(v1.y);
      }
      if (EPI == 2){
        float2 r0 = *(const float2*)&res[(size_t)row0 * N + col];
        float2 r1 = *(const float2*)&res[(size_t)(row0 + 8) * N + col];
        v0.x += r0.x; v0.y += r0.y;
        v1.x += r1.x; v1.y += r1.y;
      }
      if (ROUT){
        v0.x = tf32r(v0.x); v0.y = tf32r(v0.y);
        v1.x = tf32r(v1.x); v1.y = tf32r(v1.y);
      }
      *(float2*)&C[(size_t)row0 * N + col]       = v0;
      *(float2*)&C[(size_t)(row0 + 8) * N + col] = v1;
    }
  }
}

// ---- flash attention fp32 causal, row-major tf32-rounded output ----
#define QS_STRIDE 132
#define PS_STRIDE 80
#define ATTN_SMEM ((64*QS_STRIDE*2 + 64*128 + 64*PS_STRIDE) * 4)

__global__ __launch_bounds__(256, 1) void attn_kernel(
    const float* __restrict__ qkv, float* __restrict__ av)
{
  extern __shared__ float smem[];
  float* Qs = smem;
  float* Ks = Qs + 64 * QS_STRIDE;
  float* Vs = Ks + 64 * QS_STRIDE;
  float* Ps = Vs + 64 * 128;

  int qt = blockIdx.x;
  int bh = blockIdx.y;
  int b = bh >> 4, h = bh & 15;
  int q0 = qt * 64;
  int tid = threadIdx.x;
  int tx = tid & 15, ty = tid >> 4;
  const float* base = qkv + (size_t)(b * SEQ) * (3 * DMODEL) + h * 128;

  #pragma unroll
  for (int it = 0; it < 8; it++){
    int slot = tid + it * 256;
    int r = slot >> 5, d4 = slot & 31;
    *(float4*)&Qs[r * QS_STRIDE + d4 * 4] =
      *(const float4*)(base + (size_t)(q0 + r) * (3 * DMODEL) + d4 * 4);
  }

  float m_s[4], l_s[4], O[4][8];
  #pragma unroll
  for (int j = 0; j < 4; j++){
    m_s[j] = -1e30f; l_s[j] = 0.f;
    #pragma unroll
    for (int i = 0; i < 8; i++) O[j][i] = 0.f;
  }
  const float sc = 0.08838834764831845f;

  for (int kt = 0; kt <= qt; kt++){
    int k0 = kt * 64;
    __syncthreads();
    #pragma unroll
    for (int it = 0; it < 8; it++){
      int slot = tid + it * 256;
      int r = slot >> 5, d4 = slot & 31;
      const float* kp = base + DMODEL + (size_t)(k0 + r) * (3 * DMODEL) + d4 * 4;
      *(float4*)&Ks[r * QS_STRIDE + d4 * 4] = *(const float4*)kp;
      *(float4*)&Vs[r * 128 + d4 * 4]       = *(const float4*)(kp + DMODEL);
    }
    __syncthreads();

    float acc[4][4];
    #pragma unroll
    for (int j = 0; j < 4; j++)
      #pragma unroll
      for (int i = 0; i < 4; i++) acc[j][i] = 0.f;

    #pragma unroll 4
    for (int d4 = 0; d4 < 32; d4++){
      float4 qf[4], kf[4];
      #pragma unroll
      for (int j = 0; j < 4; j++) qf[j] = *(float4*)&Qs[(ty + 16*j) * QS_STRIDE + 4*d4];
      #pragma unroll
      for (int i = 0; i < 4; i++) kf[i] = *(float4*)&Ks[(tx + 16*i) * QS_STRIDE + 4*d4];
      #pragma unroll
      for (int j = 0; j < 4; j++)
        #pragma unroll
        for (int i = 0; i < 4; i++){
          acc[j][i] = fmaf(qf[j].x, kf[i].x, acc[j][i]);
          acc[j][i] = fmaf(qf[j].y, kf[i].y, acc[j][i]);
          acc[j][i] = fmaf(qf[j].z, kf[i].z, acc[j][i]);
          acc[j][i] = fmaf(qf[j].w, kf[i].w, acc[j][i]);
        }
    }

    bool diag = (kt == qt);
    #pragma unroll
    for (int j = 0; j < 4; j++){
      int rloc = ty + 16 * j;
      float rmax = -1e30f;
      #pragma unroll
      for (int i = 0; i < 4; i++){
        float s = acc[j][i] * sc;
        if (diag && (tx + 16 * i) > rloc) s = -1e30f;
        acc[j][i] = s;
        rmax = fmaxf(rmax, s);
      }
      #pragma unroll
      for (int m = 1; m < 16; m <<= 1)
        rmax = fmaxf(rmax, __shfl_xor_sync(0xffffffffu, rmax, m));
      float m_new = fmaxf(m_s[j], rmax);
      float corr = expf(m_s[j] - m_new);
      m_s[j] = m_new;
      float rsum = 0.f;
      #pragma unroll
      for (int i = 0; i < 4; i++){
        float p = expf(acc[j][i] - m_new);
        acc[j][i] = p;
        rsum += p;
      }
      #pragma unroll
      for (int m = 1; m < 16; m <<= 1)
        rsum += __shfl_xor_sync(0xffffffffu, rsum, m);
      l_s[j] = l_s[j] * corr + rsum;
      #pragma unroll
      for (int i = 0; i < 8; i++) O[j][i] *= corr;
      #pragma unroll
      for (int i = 0; i < 4; i++)
        Ps[rloc * PS_STRIDE + tx + 16 * i] = acc[j][i];
    }
    __syncthreads();

    #pragma unroll 4
    for (int kk = 0; kk < 64; kk++){
      float pj[4];
      #pragma unroll
      for (int j = 0; j < 4; j++) pj[j] = Ps[(ty + 16*j) * PS_STRIDE + kk];
      float4 v0 = *(float4*)&Vs[kk * 128 + 4 * tx];
      float4 v1 = *(float4*)&Vs[kk * 128 + 64 + 4 * tx];
      #pragma unroll
      for (int j = 0; j < 4; j++){
        O[j][0] = fmaf(pj[j], v0.x, O[j][0]);
        O[j][1] = fmaf(pj[j], v0.y, O[j][1]);
        O[j][2] = fmaf(pj[j], v0.z, O[j][2]);
        O[j][3] = fmaf(pj[j], v0.w, O[j][3]);
        O[j][4] = fmaf(pj[j], v1.x, O[j][4]);
        O[j][5] = fmaf(pj[j], v1.y, O[j][5]);
        O[j][6] = fmaf(pj[j], v1.z, O[j][6]);
        O[j][7] = fmaf(pj[j], v1.w, O[j][7]);
      }
    }
  }

  float* obase = av + (size_t)(b * SEQ + q0) * DMODEL + h * 128;
  #pragma unroll
  for (int j = 0; j < 4; j++){
    float inv = 1.0f / l_s[j];
    float4 o0, o1;
    o0.x = tf32r(O[j][0] * inv); o0.y = tf32r(O[j][1] * inv);
    o0.z = tf32r(O[j][2] * inv); o0.w = tf32r(O[j][3] * inv);
    o1.x = tf32r(O[j][4] * inv); o1.y = tf32r(O[j][5] * inv);
    o1.z = tf32r(O[j][6] * inv); o1.w = tf32r(O[j][7] * inv);
    float* orow = obase + (size_t)(ty + 16 * j) * DMODEL;
    *(float4*)&orow[4 * tx]      = o0;
    *(float4*)&orow[64 + 4 * tx] = o1;
  }
}

// ---------------- launch ----------------
extern "C" void kernel_launch(void* const* d_in, const int* in_sizes, int n_in,
                              void* d_out, int out_size)
{
  const float* x     = (const float*)d_in[0];
  const float* ln1_g = (const float*)d_in[1];
  const float* ln1_b = (const float*)d_in[2];
  const float* qkv_w = (const float*)d_in[3];
  const float* qkv_b = (const float*)d_in[4];
  const float* out_w = (const float*)d_in[5];
  const float* out_b = (const float*)d_in[6];
  const float* ln2_g = (const float*)d_in[7];
  const float* ln2_b = (const float*)d_in[8];
  const float* w1    = (const float*)d_in[9];
  const float* b1    = (const float*)d_in[10];
  const float* w2    = (const float*)d_in[11];
  const float* b2    = (const float*)d_in[12];
  float* out = (float*)d_out;

  float *h_p, *qkv_p, *av_p, *x1_p, *ffn_p, *wqkv_p, *wout_p, *w1_p, *w2_p;
  cudaGetSymbolAddress((void**)&h_p,    g_h);
  cudaGetSymbolAddress((void**)&qkv_p,  g_qkv);
  cudaGetSymbolAddress((void**)&av_p,   g_av);
  cudaGetSymbolAddress((void**)&x1_p,   g_x1);
  cudaGetSymbolAddress((void**)&ffn_p,  g_ffn);
  cudaGetSymbolAddress((void**)&wqkv_p, g_wqkv_r);
  cudaGetSymbolAddress((void**)&wout_p, g_wout_r);
  cudaGetSymbolAddress((void**)&w1_p,   g_w1_r);
  cudaGetSymbolAddress((void**)&w2_p,   g_w2_r);

  cudaFuncSetAttribute(attn_kernel, cudaFuncAttributeMaxDynamicSharedMemorySize, ATTN_SMEM);

  // round weights to tf32 (once per launch; cheap)
  round_kernel<<<3 * DMODEL * DMODEL / 1024, 256>>>(qkv_w, wqkv_p);
  round_kernel<<<DMODEL * DMODEL / 1024, 256>>>(out_w, wout_p);
  round_kernel<<<DMODEL * FFDIM / 1024, 256>>>(w1, w1_p);
  round_kernel<<<FFDIM * DMODEL / 1024, 256>>>(w2, w2_p);

  // 1. LN1 -> rounded
  ln_kernel<<<NTOK, 256>>>(x, ln1_g, ln1_b, h_p);

  // 2. QKV = h @ qkv_w + b (fp32 out, feeds fp32 attention)
  tfgemm<0,0><<<dim3(48, 32), 256>>>(h_p, wqkv_p, qkv_b, nullptr, qkv_p,
                                     NTOK, 3 * DMODEL, DMODEL);

  // 3. attention -> rounded row-major
  attn_kernel<<<dim3(SEQ / 64, 2 * NHEAD), 256, ATTN_SMEM>>>(qkv_p, av_p);

  // 4. x1 = x + av @ out_w + out_b (fp32)
  tfgemm<2,0><<<dim3(16, 32), 256>>>(av_p, wout_p, out_b, x, x1_p,
                                     NTOK, DMODEL, DMODEL);

  // 5. LN2 -> rounded
  ln_kernel<<<NTOK, 256>>>(x1_p, ln2_g, ln2_b, h_p);

  // 6. ffn = gelu(h @ w1 + b1) -> rounded
  tfgemm<1,1><<<dim3(64, 32), 256>>>(h_p, w1_p, b1, nullptr, ffn_p,
                                     NTOK, FFDIM, DMODEL);

  // 7. out = x1 + ffn @ w2 + b2 (fp32)
  tfgemm<2,0><<<dim3(16, 32), 256>>>(ffn_p, w2_p, b2, x1_p, out,
                                     NTOK, DMODEL, FFDIM);
}

// round 5
// speedup vs baseline: 4.4557x; 1.2164x over previous
#include <cuda_runtime.h>
#include <math.h>
#include <stdint.h>

#define SEQ     2048
#define DMODEL  2048
#define NHEAD   16
#define FFDIM   8192
#define NTOK    4096
#define LN_EPS  1e-5f

__device__ float g_h  [(size_t)NTOK * DMODEL];
__device__ float g_qkv[(size_t)NTOK * 3 * DMODEL];
__device__ float g_av [(size_t)NTOK * DMODEL];
__device__ float g_x1 [(size_t)NTOK * DMODEL];
__device__ float g_ffn[(size_t)NTOK * FFDIM];
__device__ float g_wqkv_r[(size_t)3 * DMODEL * DMODEL];
__device__ float g_wout_r[(size_t)DMODEL * DMODEL];
__device__ float g_w1_r  [(size_t)DMODEL * FFDIM];
__device__ float g_w2_r  [(size_t)FFDIM * DMODEL];

// ---------------- helpers ----------------
__device__ __forceinline__ float tf32r(float x){
  uint32_t u; asm("cvt.rna.tf32.f32 %0, %1;" : "=r"(u) : "f"(x));
  return __uint_as_float(u);
}
__device__ __forceinline__ uint32_t s2u(const void* p){
  uint32_t a;
  asm("{ .reg .u64 t; cvta.to.shared.u64 t, %1; cvt.u32.u64 %0, t; }" : "=r"(a) : "l"(p));
  return a;
}
__device__ __forceinline__ void cpa16(uint32_t dst, const void* src){
  asm volatile("cp.async.cg.shared.global [%0], [%1], 16;" :: "r"(dst), "l"(src));
}
__device__ __forceinline__ void cp_commit(){ asm volatile("cp.async.commit_group;"); }
__device__ __forceinline__ void cp_wait0(){ asm volatile("cp.async.wait_group 0;" ::: "memory"); }
__device__ __forceinline__ void cp_wait1(){ asm volatile("cp.async.wait_group 1;" ::: "memory"); }
__device__ __forceinline__ void mma8(float* c, const uint32_t* a, const uint32_t* b){
  asm volatile("mma.sync.aligned.m16n8k8.row.col.f32.tf32.tf32.f32 "
    "{%0,%1,%2,%3}, {%4,%5,%6,%7}, {%8,%9}, {%0,%1,%2,%3};"
    : "+f"(c[0]), "+f"(c[1]), "+f"(c[2]), "+f"(c[3])
    : "r"(a[0]), "r"(a[1]), "r"(a[2]), "r"(a[3]), "r"(b[0]), "r"(b[1]));
}
__device__ __forceinline__ float gelu_exact(float t){
  return 0.5f * t * (1.0f + erff(t * 0.70710678118654752f));
}

// ---- elementwise tf32 round (weights) ----
__global__ __launch_bounds__(256) void round_kernel(
    const float* __restrict__ in, float* __restrict__ out)
{
  size_t i = (size_t)blockIdx.x * 256 + threadIdx.x;
  float4 v = ((const float4*)in)[i];
  v.x = tf32r(v.x); v.y = tf32r(v.y); v.z = tf32r(v.z); v.w = tf32r(v.w);
  ((float4*)out)[i] = v;
}

// ---- LayerNorm -> row-major tf32-rounded ----
__global__ __launch_bounds__(256) void ln_kernel(
    const float* __restrict__ x, const float* __restrict__ gamma,
    const float* __restrict__ beta, float* __restrict__ out)
{
  int row = blockIdx.x;
  int tid = threadIdx.x;
  const float4* xr = (const float4*)(x + (size_t)row * DMODEL);
  float4 v0 = xr[tid];
  float4 v1 = xr[tid + 256];
  float s  = v0.x + v0.y + v0.z + v0.w + v1.x + v1.y + v1.z + v1.w;
  float sq = v0.x*v0.x + v0.y*v0.y + v0.z*v0.z + v0.w*v0.w
           + v1.x*v1.x + v1.y*v1.y + v1.z*v1.z + v1.w*v1.w;
  #pragma unroll
  for (int m = 16; m > 0; m >>= 1){
    s  += __shfl_xor_sync(0xffffffffu, s,  m);
    sq += __shfl_xor_sync(0xffffffffu, sq, m);
  }
  __shared__ float red_s[8], red_q[8], bc[2];
  int warp = tid >> 5, lane = tid & 31;
  if (lane == 0){ red_s[warp] = s; red_q[warp] = sq; }
  __syncthreads();
  if (tid == 0){
    float ts = 0.f, tq = 0.f;
    #pragma unroll
    for (int i = 0; i < 8; i++){ ts += red_s[i]; tq += red_q[i]; }
    float mu  = ts * (1.0f / DMODEL);
    float var = tq * (1.0f / DMODEL) - mu * mu;
    bc[0] = mu; bc[1] = rsqrtf(var + LN_EPS);
  }
  __syncthreads();
  float mu = bc[0], rinv = bc[1];
  const float4* gv = (const float4*)gamma;
  const float4* bv = (const float4*)beta;
  float4 g0 = gv[tid], b0 = bv[tid];
  float4 g1 = gv[tid + 256], b1 = bv[tid + 256];
  float4 o0, o1;
  o0.x = tf32r((v0.x - mu) * rinv * g0.x + b0.x);
  o0.y = tf32r((v0.y - mu) * rinv * g0.y + b0.y);
  o0.z = tf32r((v0.z - mu) * rinv * g0.z + b0.z);
  o0.w = tf32r((v0.w - mu) * rinv * g0.w + b0.w);
  o1.x = tf32r((v1.x - mu) * rinv * g1.x + b1.x);
  o1.y = tf32r((v1.y - mu) * rinv * g1.y + b1.y);
  o1.z = tf32r((v1.z - mu) * rinv * g1.z + b1.z);
  o1.w = tf32r((v1.w - mu) * rinv * g1.w + b1.w);
  float4* ov = (float4*)(out + (size_t)row * DMODEL);
  ov[tid]       = o0;
  ov[tid + 256] = o1;
}

// ---------------------------------------------------------------------------
// tf32 mma.sync GEMM (as R4). EPI: 0=bias,1=+gelu,2=+residual. ROUT: tf32 out.
// ---------------------------------------------------------------------------
template<int EPI, int ROUT>
__global__ __launch_bounds__(256, 2) void tfgemm(
    const float* __restrict__ A, const float* __restrict__ B,
    const float* __restrict__ bias, const float* __restrict__ res,
    float* __restrict__ C, int M, int N, int K)
{
  __shared__ float As[2][128][20];
  __shared__ float Bs[2][16][136];

  int tid = threadIdx.x, lane = tid & 31, warp = tid >> 5;
  int bx = blockIdx.x, by = blockIdx.y;
  int wm = (warp >> 2) * 64, wn = (warp & 3) * 32;
  int gid = lane >> 2, tig = lane & 3;

  int a_r0 = tid >> 2;
  int a_k4 = (tid & 3) * 4;
  int b_k0 = tid >> 5;
  int b_n4 = (tid & 31) * 4;

  const float* Ag = A + (size_t)(by * 128 + a_r0) * K + a_k4;
  const float* Bg = B + (size_t)b_k0 * N + bx * 128 + b_n4;

  uint32_t as_d0 = s2u(&As[0][a_r0][a_k4]);
  uint32_t as_d1 = s2u(&As[0][a_r0 + 64][a_k4]);
  uint32_t bs_d0 = s2u(&Bs[0][b_k0][b_n4]);
  uint32_t bs_d1 = s2u(&Bs[0][b_k0 + 8][b_n4]);
  const uint32_t aSt = sizeof(float) * 128 * 20;
  const uint32_t bSt = sizeof(float) * 16 * 136;

  float c[4][4][4];
  #pragma unroll
  for (int mi = 0; mi < 4; mi++)
    #pragma unroll
    for (int ni = 0; ni < 4; ni++)
      #pragma unroll
      for (int q = 0; q < 4; q++) c[mi][ni][q] = 0.f;

  int nk = K >> 4;
  cpa16(as_d0, Ag);
  cpa16(as_d1, Ag + (size_t)64 * K);
  cpa16(bs_d0, Bg);
  cpa16(bs_d1, Bg + (size_t)8 * N);
  cp_commit();

  int st = 0;
  for (int kb = 0; kb < nk; kb++){
    cp_wait0();
    __syncthreads();
    if (kb + 1 < nk){
      const float* Agn = Ag + (kb + 1) * 16;
      const float* Bgn = Bg + (size_t)(kb + 1) * 16 * N;
      uint32_t so = (st ^ 1) ? aSt : 0;
      uint32_t sb = (st ^ 1) ? bSt : 0;
      cpa16(as_d0 + so, Agn);
      cpa16(as_d1 + so, Agn + (size_t)64 * K);
      cpa16(bs_d0 + sb, Bgn);
      cpa16(bs_d1 + sb, Bgn + (size_t)8 * N);
      cp_commit();
    }
    #pragma unroll
    for (int ks = 0; ks < 2; ks++){
      int k0 = ks * 8;
      uint32_t a[4][4], b[4][2];
      #pragma unroll
      for (int mi = 0; mi < 4; mi++){
        int r0 = wm + mi * 16 + gid;
        a[mi][0] = __float_as_uint(As[st][r0][k0 + tig]);
        a[mi][1] = __float_as_uint(As[st][r0 + 8][k0 + tig]);
        a[mi][2] = __float_as_uint(As[st][r0][k0 + tig + 4]);
        a[mi][3] = __float_as_uint(As[st][r0 + 8][k0 + tig + 4]);
      }
      #pragma unroll
      for (int ni = 0; ni < 4; ni++){
        int n0 = wn + ni * 8 + gid;
        b[ni][0] = __float_as_uint(Bs[st][k0 + tig][n0]);
        b[ni][1] = __float_as_uint(Bs[st][k0 + tig + 4][n0]);
      }
      #pragma unroll
      for (int mi = 0; mi < 4; mi++)
        #pragma unroll
        for (int ni = 0; ni < 4; ni++)
          mma8(c[mi][ni], a[mi], b[ni]);
    }
    st ^= 1;
    __syncthreads();
  }

  #pragma unroll
  for (int ni = 0; ni < 4; ni++){
    int col = bx * 128 + wn + ni * 8 + 2 * tig;
    float bb0 = bias[col], bb1 = bias[col + 1];
    #pragma unroll
    for (int mi = 0; mi < 4; mi++){
      int row0 = by * 128 + wm + mi * 16 + gid;
      float2 v0, v1;
      v0.x = c[mi][ni][0] + bb0; v0.y = c[mi][ni][1] + bb1;
      v1.x = c[mi][ni][2] + bb0; v1.y = c[mi][ni][3] + bb1;
      if (EPI == 1){
        v0.x = gelu_exact(v0.x); v0.y = gelu_exact(v0.y);
        v1.x = gelu_exact(v1.x); v1.y = gelu_exact(v1.y);
      }
      if (EPI == 2){
        float2 r0 = *(const float2*)&res[(size_t)row0 * N + col];
        float2 r1 = *(const float2*)&res[(size_t)(row0 + 8) * N + col];
        v0.x += r0.x; v0.y += r0.y;
        v1.x += r1.x; v1.y += r1.y;
      }
      if (ROUT){
        v0.x = tf32r(v0.x); v0.y = tf32r(v0.y);
        v1.x = tf32r(v1.x); v1.y = tf32r(v1.y);
      }
      *(float2*)&C[(size_t)row0 * N + col]       = v0;
      *(float2*)&C[(size_t)(row0 + 8) * N + col] = v1;
    }
  }
}

// ---------------------------------------------------------------------------
// tf32 mma.sync flash attention, causal. CTA: 128 queries x (b,h). 8 warps,
// each owns 16 query rows. K-tiles of 64, cp.async double-buffered K/V.
// smem floats: KV stages [2][K 64x132 | V 64x132], Ps [128][68].
// ---------------------------------------------------------------------------
#define AT_TILE_F  8448              // 64*132
#define AT_BUF_F   16896             // K+V per stage
#define AT_PS_F    33792             // 2 stages
#define AT_SMEM    ((AT_PS_F + 128 * 68) * 4)

__global__ __launch_bounds__(256, 1) void attn_mma_kernel(
    const float* __restrict__ qkv, float* __restrict__ av)
{
  extern __shared__ float sm[];
  float* Ps = sm + AT_PS_F;
  uint32_t sbase = s2u(sm);

  int qt = blockIdx.x, bh = blockIdx.y;
  int b = bh >> 4, h = bh & 15;
  int q0 = qt * 128;
  int tid = threadIdx.x, warp = tid >> 5, lane = tid & 31;
  int gid = lane >> 2, tig = lane & 3;
  int wq = warp * 16;
  const float scl = 0.08838834764831845f;

  const float* base = qkv + (size_t)(b * SEQ) * (3 * DMODEL) + h * 128;

  // Q fragments in registers (rows r0, r0+8; 16 k-steps)
  int r0 = q0 + wq + gid;          // sequence-local query row
  const float* Qp0 = base + (size_t)r0 * (3 * DMODEL);
  const float* Qp1 = Qp0 + (size_t)8 * (3 * DMODEL);
  uint32_t qa[16][4];
  #pragma unroll
  for (int ks = 0; ks < 16; ks++){
    qa[ks][0] = __float_as_uint(__ldg(Qp0 + 8 * ks + tig));
    qa[ks][1] = __float_as_uint(__ldg(Qp1 + 8 * ks + tig));
    qa[ks][2] = __float_as_uint(__ldg(Qp0 + 8 * ks + tig + 4));
    qa[ks][3] = __float_as_uint(__ldg(Qp1 + 8 * ks + tig + 4));
  }

  float O[16][4];
  #pragma unroll
  for (int u = 0; u < 16; u++)
    #pragma unroll
    for (int q = 0; q < 4; q++) O[u][q] = 0.f;
  float m0 = -1e30f, m1 = -1e30f, l0 = 0.f, l1 = 0.f;

  int ntiles = 2 * qt + 2;

  // prefetch helper: K/V tile kt -> stage buf
  int pf_r  = tid >> 5;            // 0..7 (+8 per it)
  int pf_d4 = (tid & 31) * 4;
  // issue tile 0
  {
    const float* kg = base + DMODEL + (size_t)pf_r * (3 * DMODEL) + pf_d4;
    #pragma unroll
    for (int it = 0; it < 8; it++){
      uint32_t dk = sbase + ((pf_r + it * 8) * 132 + pf_d4) * 4;
      const float* src = kg + (size_t)(it * 8) * (3 * DMODEL);
      cpa16(dk, src);
      cpa16(dk + AT_TILE_F * 4, src + DMODEL);
    }
    cp_commit();
  }

  for (int kt = 0; kt < ntiles; kt++){
    int buf = kt & 1;
    if (kt + 1 < ntiles){
      int k0n = (kt + 1) * 64;
      const float* kg = base + DMODEL + (size_t)(k0n + pf_r) * (3 * DMODEL) + pf_d4;
      uint32_t db = sbase + ((buf ^ 1) * AT_BUF_F) * 4;
      #pragma unroll
      for (int it = 0; it < 8; it++){
        uint32_t dk = db + ((pf_r + it * 8) * 132 + pf_d4) * 4;
        const float* src = kg + (size_t)(it * 8) * (3 * DMODEL);
        cpa16(dk, src);
        cpa16(dk + AT_TILE_F * 4, src + DMODEL);
      }
      cp_commit();
      cp_wait1();
    } else {
      cp_wait0();
    }
    __syncthreads();

    int k0 = kt * 64;
    bool active = (k0 <= q0 + wq + 15);
    if (active){
      const float* Ks = sm + buf * AT_BUF_F;
      const float* Vs = Ks + AT_TILE_F;

      // S = Q @ K^T   (8 n8 tiles over 64 keys)
      float s[8][4];
      #pragma unroll
      for (int t = 0; t < 8; t++)
        #pragma unroll
        for (int q = 0; q < 4; q++) s[t][q] = 0.f;
      #pragma unroll
      for (int ks = 0; ks < 16; ks++){
        uint32_t bf[8][2];
        #pragma unroll
        for (int t = 0; t < 8; t++){
          int n0 = 8 * t + gid;
          bf[t][0] = __float_as_uint(Ks[n0 * 132 + 8 * ks + tig]);
          bf[t][1] = __float_as_uint(Ks[n0 * 132 + 8 * ks + tig + 4]);
        }
        #pragma unroll
        for (int t = 0; t < 8; t++)
          mma8(s[t], qa[ks], bf[t]);
      }

      // scale + causal mask + online softmax (rows fully warp-local)
      bool dg = (kt >= 2 * qt);
      float mx0 = -1e30f, mx1 = -1e30f;
      #pragma unroll
      for (int t = 0; t < 8; t++){
        float c0 = s[t][0] * scl, c1 = s[t][1] * scl;
        float c2 = s[t][2] * scl, c3 = s[t][3] * scl;
        if (dg){
          int g0 = k0 + 8 * t + 2 * tig;
          if (g0     > r0)     c0 = -1e30f;
          if (g0 + 1 > r0)     c1 = -1e30f;
          if (g0     > r0 + 8) c2 = -1e30f;
          if (g0 + 1 > r0 + 8) c3 = -1e30f;
        }
        s[t][0] = c0; s[t][1] = c1; s[t][2] = c2; s[t][3] = c3;
        mx0 = fmaxf(mx0, fmaxf(c0, c1));
        mx1 = fmaxf(mx1, fmaxf(c2, c3));
      }
      #pragma unroll
      for (int m = 1; m < 4; m <<= 1){
        mx0 = fmaxf(mx0, __shfl_xor_sync(0xffffffffu, mx0, m));
        mx1 = fmaxf(mx1, __shfl_xor_sync(0xffffffffu, mx1, m));
      }
      float mn0 = fmaxf(m0, mx0), mn1 = fmaxf(m1, mx1);
      float cr0 = __expf(m0 - mn0), cr1 = __expf(m1 - mn1);
      m0 = mn0; m1 = mn1;
      float ls0 = 0.f, ls1 = 0.f;
      int lr0 = wq + gid, lr1 = wq + gid + 8;
      #pragma unroll
      for (int t = 0; t < 8; t++){
        float p0 = __expf(s[t][0] - mn0);
        float p1 = __expf(s[t][1] - mn0);
        float p2 = __expf(s[t][2] - mn1);
        float p3 = __expf(s[t][3] - mn1);
        ls0 += p0 + p1; ls1 += p2 + p3;
        float2 w0 = make_float2(tf32r(p0), tf32r(p1));
        float2 w1 = make_float2(tf32r(p2), tf32r(p3));
        *(float2*)&Ps[lr0 * 68 + 8 * t + 2 * tig] = w0;
        *(float2*)&Ps[lr1 * 68 + 8 * t + 2 * tig] = w1;
      }
      #pragma unroll
      for (int m = 1; m < 4; m <<= 1){
        ls0 += __shfl_xor_sync(0xffffffffu, ls0, m);
        ls1 += __shfl_xor_sync(0xffffffffu, ls1, m);
      }
      l0 = l0 * cr0 + ls0;
      l1 = l1 * cr1 + ls1;
      #pragma unroll
      for (int u = 0; u < 16; u++){
        O[u][0] *= cr0; O[u][1] *= cr0;
        O[u][2] *= cr1; O[u][3] *= cr1;
      }
      __syncwarp();

      // O += P @ V   (16 n8 tiles over 128 d, 8 k-steps over 64 keys)
      #pragma unroll
      for (int ks = 0; ks < 8; ks++){
        uint32_t a[4];
        a[0] = __float_as_uint(Ps[lr0 * 68 + 8 * ks + tig]);
        a[1] = __float_as_uint(Ps[lr1 * 68 + 8 * ks + tig]);
        a[2] = __float_as_uint(Ps[lr0 * 68 + 8 * ks + tig + 4]);
        a[3] = __float_as_uint(Ps[lr1 * 68 + 8 * ks + tig + 4]);
        #pragma unroll
        for (int u = 0; u < 16; u++){
          uint32_t bf[2];
          bf[0] = __float_as_uint(Vs[(8 * ks + tig) * 132 + 8 * u + gid]);
          bf[1] = __float_as_uint(Vs[(8 * ks + tig + 4) * 132 + 8 * u + gid]);
          mma8(O[u], a, bf);
        }
      }
      __syncwarp();
    }
    __syncthreads();
  }

  // epilogue
  float i0 = 1.0f / l0, i1 = 1.0f / l1;
  float* o0 = av + ((size_t)(b * SEQ) + r0) * DMODEL + h * 128;
  float* o1 = o0 + (size_t)8 * DMODEL;
  #pragma unroll
  for (int u = 0; u < 16; u++){
    float2 v0 = make_float2(tf32r(O[u][0] * i0), tf32r(O[u][1] * i0));
    float2 v1 = make_float2(tf32r(O[u][2] * i1), tf32r(O[u][3] * i1));
    *(float2*)&o0[8 * u + 2 * tig] = v0;
    *(float2*)&o1[8 * u + 2 * tig] = v1;
  }
}

// ---------------- launch ----------------
extern "C" void kernel_launch(void* const* d_in, const int* in_sizes, int n_in,
                              void* d_out, int out_size)
{
  const float* x     = (const float*)d_in[0];
  const float* ln1_g = (const float*)d_in[1];
  const float* ln1_b = (const float*)d_in[2];
  const float* qkv_w = (const float*)d_in[3];
  const float* qkv_b = (const float*)d_in[4];
  const float* out_w = (const float*)d_in[5];
  const float* out_b = (const float*)d_in[6];
  const float* ln2_g = (const float*)d_in[7];
  const float* ln2_b = (const float*)d_in[8];
  const float* w1    = (const float*)d_in[9];
  const float* b1    = (const float*)d_in[10];
  const float* w2    = (const float*)d_in[11];
  const float* b2    = (const float*)d_in[12];
  float* out = (float*)d_out;

  float *h_p, *qkv_p, *av_p, *x1_p, *ffn_p, *wqkv_p, *wout_p, *w1_p, *w2_p;
  cudaGetSymbolAddress((void**)&h_p,    g_h);
  cudaGetSymbolAddress((void**)&qkv_p,  g_qkv);
  cudaGetSymbolAddress((void**)&av_p,   g_av);
  cudaGetSymbolAddress((void**)&x1_p,   g_x1);
  cudaGetSymbolAddress((void**)&ffn_p,  g_ffn);
  cudaGetSymbolAddress((void**)&wqkv_p, g_wqkv_r);
  cudaGetSymbolAddress((void**)&wout_p, g_wout_r);
  cudaGetSymbolAddress((void**)&w1_p,   g_w1_r);
  cudaGetSymbolAddress((void**)&w2_p,   g_w2_r);

  cudaFuncSetAttribute(attn_mma_kernel, cudaFuncAttributeMaxDynamicSharedMemorySize, AT_SMEM);

  round_kernel<<<3 * DMODEL * DMODEL / 1024, 256>>>(qkv_w, wqkv_p);
  round_kernel<<<DMODEL * DMODEL / 1024, 256>>>(out_w, wout_p);
  round_kernel<<<DMODEL * FFDIM / 1024, 256>>>(w1, w1_p);
  round_kernel<<<FFDIM * DMODEL / 1024, 256>>>(w2, w2_p);

  // 1. LN1 -> rounded
  ln_kernel<<<NTOK, 256>>>(x, ln1_g, ln1_b, h_p);

  // 2. QKV = h @ qkv_w + b  (rounded: attention MMA consumes tf32)
  tfgemm<0,1><<<dim3(48, 32), 256>>>(h_p, wqkv_p, qkv_b, nullptr, qkv_p,
                                     NTOK, 3 * DMODEL, DMODEL);

  // 3. mma flash attention -> rounded
  attn_mma_kernel<<<dim3(SEQ / 128, 2 * NHEAD), 256, AT_SMEM>>>(qkv_p, av_p);

  // 4. x1 = x + av @ out_w + out_b (fp32)
  tfgemm<2,0><<<dim3(16, 32), 256>>>(av_p, wout_p, out_b, x, x1_p,
                                     NTOK, DMODEL, DMODEL);

  // 5. LN2 -> rounded
  ln_kernel<<<NTOK, 256>>>(x1_p, ln2_g, ln2_b, h_p);

  // 6. ffn = gelu(h @ w1 + b1) -> rounded
  tfgemm<1,1><<<dim3(64, 32), 256>>>(h_p, w1_p, b1, nullptr, ffn_p,
                                     NTOK, FFDIM, DMODEL);

  // 7. out = x1 + ffn @ w2 + b2 (fp32)
  tfgemm<2,0><<<dim3(16, 32), 256>>>(ffn_p, w2_p, b2, x1_p, out,
                                     NTOK, DMODEL, FFDIM);
}

// round 6
// speedup vs baseline: 4.4759x; 1.0045x over previous
#include <cuda_runtime.h>
#include <math.h>
#include <stdint.h>

#define SEQ     2048
#define DMODEL  2048
#define NHEAD   16
#define FFDIM   8192
#define NTOK    4096
#define LN_EPS  1e-5f

__device__ float g_h  [(size_t)NTOK * DMODEL];
__device__ float g_qkv[(size_t)NTOK * 3 * DMODEL];
__device__ float g_av [(size_t)NTOK * DMODEL];
__device__ float g_x1 [(size_t)NTOK * DMODEL];
__device__ float g_ffn[(size_t)NTOK * FFDIM];
__device__ float g_wqkv_r[(size_t)3 * DMODEL * DMODEL];
__device__ float g_wout_r[(size_t)DMODEL * DMODEL];
__device__ float g_w1_r  [(size_t)DMODEL * FFDIM];
__device__ float g_w2_r  [(size_t)FFDIM * DMODEL];

// ---------------- helpers ----------------
__device__ __forceinline__ float tf32r(float x){
  uint32_t u; asm("cvt.rna.tf32.f32 %0, %1;" : "=r"(u) : "f"(x));
  return __uint_as_float(u);
}
__device__ __forceinline__ uint32_t s2u(const void* p){
  uint32_t a;
  asm("{ .reg .u64 t; cvta.to.shared.u64 t, %1; cvt.u32.u64 %0, t; }" : "=r"(a) : "l"(p));
  return a;
}
__device__ __forceinline__ void cpa16(uint32_t dst, const void* src){
  asm volatile("cp.async.cg.shared.global [%0], [%1], 16;" :: "r"(dst), "l"(src));
}
__device__ __forceinline__ void cp_commit(){ asm volatile("cp.async.commit_group;"); }
__device__ __forceinline__ void cp_wait0(){ asm volatile("cp.async.wait_group 0;" ::: "memory"); }
__device__ __forceinline__ void cp_wait1(){ asm volatile("cp.async.wait_group 1;" ::: "memory"); }
__device__ __forceinline__ void mma8(float* c, const uint32_t* a, const uint32_t* b){
  asm volatile("mma.sync.aligned.m16n8k8.row.col.f32.tf32.tf32.f32 "
    "{%0,%1,%2,%3}, {%4,%5,%6,%7}, {%8,%9}, {%0,%1,%2,%3};"
    : "+f"(c[0]), "+f"(c[1]), "+f"(c[2]), "+f"(c[3])
    : "r"(a[0]), "r"(a[1]), "r"(a[2]), "r"(a[3]), "r"(b[0]), "r"(b[1]));
}
__device__ __forceinline__ float gelu_exact(float t){
  return 0.5f * t * (1.0f + erff(t * 0.70710678118654752f));
}

// ---- elementwise tf32 round (weights) ----
__global__ __launch_bounds__(256) void round_kernel(
    const float* __restrict__ in, float* __restrict__ out)
{
  size_t i = (size_t)blockIdx.x * 256 + threadIdx.x;
  float4 v = ((const float4*)in)[i];
  v.x = tf32r(v.x); v.y = tf32r(v.y); v.z = tf32r(v.z); v.w = tf32r(v.w);
  ((float4*)out)[i] = v;
}

// ---- LayerNorm -> row-major tf32-rounded ----
__global__ __launch_bounds__(256) void ln_kernel(
    const float* __restrict__ x, const float* __restrict__ gamma,
    const float* __restrict__ beta, float* __restrict__ out)
{
  int row = blockIdx.x;
  int tid = threadIdx.x;
  const float4* xr = (const float4*)(x + (size_t)row * DMODEL);
  float4 v0 = xr[tid];
  float4 v1 = xr[tid + 256];
  float s  = v0.x + v0.y + v0.z + v0.w + v1.x + v1.y + v1.z + v1.w;
  float sq = v0.x*v0.x + v0.y*v0.y + v0.z*v0.z + v0.w*v0.w
           + v1.x*v1.x + v1.y*v1.y + v1.z*v1.z + v1.w*v1.w;
  #pragma unroll
  for (int m = 16; m > 0; m >>= 1){
    s  += __shfl_xor_sync(0xffffffffu, s,  m);
    sq += __shfl_xor_sync(0xffffffffu, sq, m);
  }
  __shared__ float red_s[8], red_q[8], bc[2];
  int warp = tid >> 5, lane = tid & 31;
  if (lane == 0){ red_s[warp] = s; red_q[warp] = sq; }
  __syncthreads();
  if (tid == 0){
    float ts = 0.f, tq = 0.f;
    #pragma unroll
    for (int i = 0; i < 8; i++){ ts += red_s[i]; tq += red_q[i]; }
    float mu  = ts * (1.0f / DMODEL);
    float var = tq * (1.0f / DMODEL) - mu * mu;
    bc[0] = mu; bc[1] = rsqrtf(var + LN_EPS);
  }
  __syncthreads();
  float mu = bc[0], rinv = bc[1];
  const float4* gv = (const float4*)gamma;
  const float4* bv = (const float4*)beta;
  float4 g0 = gv[tid], b0 = bv[tid];
  float4 g1 = gv[tid + 256], b1 = bv[tid + 256];
  float4 o0, o1;
  o0.x = tf32r((v0.x - mu) * rinv * g0.x + b0.x);
  o0.y = tf32r((v0.y - mu) * rinv * g0.y + b0.y);
  o0.z = tf32r((v0.z - mu) * rinv * g0.z + b0.z);
  o0.w = tf32r((v0.w - mu) * rinv * g0.w + b0.w);
  o1.x = tf32r((v1.x - mu) * rinv * g1.x + b1.x);
  o1.y = tf32r((v1.y - mu) * rinv * g1.y + b1.y);
  o1.z = tf32r((v1.z - mu) * rinv * g1.z + b1.z);
  o1.w = tf32r((v1.w - mu) * rinv * g1.w + b1.w);
  float4* ov = (float4*)(out + (size_t)row * DMODEL);
  ov[tid]       = o0;
  ov[tid + 256] = o1;
}

// ---------------------------------------------------------------------------
// tf32 mma.sync GEMM v2. CTA tile 128x256, BK=16, 256 thr, 8 warps (2x4),
// warp tile 64x64 (4 m-tiles x 8 n-tiles). 3-stage cp.async pipeline.
// A,B row-major tf32-rounded. EPI: 0=bias,1=+gelu,2=+residual. ROUT: tf32 out.
// ---------------------------------------------------------------------------
#define G2_AF    (128 * 20)          // A tile floats (padded)
#define G2_BF    (16 * 264)          // B tile floats (padded)
#define G2_STF   (G2_AF + G2_BF)     // stage floats = 6784
#define G2_SMEM  (3 * G2_STF * 4)    // 81408 bytes

template<int EPI, int ROUT>
__global__ __launch_bounds__(256, 1) void tfgemm2(
    const float* __restrict__ A, const float* __restrict__ B,
    const float* __restrict__ bias, const float* __restrict__ res,
    float* __restrict__ C, int M, int N, int K)
{
  extern __shared__ float sm[];
  int tid = threadIdx.x, lane = tid & 31, warp = tid >> 5;
  int bx = blockIdx.x, by = blockIdx.y;
  int wm = (warp >> 2) * 64, wn = (warp & 3) * 64;
  int gid = lane >> 2, tig = lane & 3;

  int a_r0 = tid >> 2;               // 0..63  (also +64)
  int a_k4 = (tid & 3) * 4;
  int b_k0 = tid >> 6;               // 0..3   (also +4,+8,+12)
  int b_n4 = (tid & 63) * 4;

  const float* Ag = A + (size_t)(by * 128 + a_r0) * K + a_k4;
  const float* Bg = B + (size_t)b_k0 * N + bx * 256 + b_n4;

  uint32_t smb = s2u(sm);
  uint32_t asd0 = smb + (a_r0 * 20 + a_k4) * 4;
  uint32_t asd1 = smb + ((a_r0 + 64) * 20 + a_k4) * 4;
  uint32_t bsd  = smb + (G2_AF + b_k0 * 264 + b_n4) * 4;

  float c[4][8][4];
  #pragma unroll
  for (int mi = 0; mi < 4; mi++)
    #pragma unroll
    for (int ni = 0; ni < 8; ni++)
      #pragma unroll
      for (int q = 0; q < 4; q++) c[mi][ni][q] = 0.f;

  int nk = K >> 4;

  // issue stage for k-block kb into slot st
  auto issue = [&](int kb, int st){
    uint32_t off = (uint32_t)st * G2_STF * 4;
    const float* Agn = Ag + kb * 16;
    const float* Bgn = Bg + (size_t)kb * 16 * N;
    cpa16(asd0 + off, Agn);
    cpa16(asd1 + off, Agn + (size_t)64 * K);
    #pragma unroll
    for (int i = 0; i < 4; i++)
      cpa16(bsd + off + i * 4 * 264 * 4, Bgn + (size_t)(4 * i) * N);
    cp_commit();
  };

  issue(0, 0);
  if (nk > 1) issue(1, 1);

  for (int kb = 0; kb < nk; kb++){
    int st = kb % 3;
    if (kb + 1 < nk) cp_wait1(); else cp_wait0();
    __syncthreads();

    const float* As = sm + st * G2_STF;
    const float* Bs = As + G2_AF;
    #pragma unroll
    for (int ks = 0; ks < 2; ks++){
      int k0 = ks * 8;
      uint32_t a[4][4], b[8][2];
      #pragma unroll
      for (int mi = 0; mi < 4; mi++){
        int r0 = wm + mi * 16 + gid;
        a[mi][0] = __float_as_uint(As[r0 * 20 + k0 + tig]);
        a[mi][1] = __float_as_uint(As[(r0 + 8) * 20 + k0 + tig]);
        a[mi][2] = __float_as_uint(As[r0 * 20 + k0 + tig + 4]);
        a[mi][3] = __float_as_uint(As[(r0 + 8) * 20 + k0 + tig + 4]);
      }
      #pragma unroll
      for (int t = 0; t < 8; t++){
        int n0 = wn + 8 * t + gid;
        b[t][0] = __float_as_uint(Bs[(k0 + tig) * 264 + n0]);
        b[t][1] = __float_as_uint(Bs[(k0 + tig + 4) * 264 + n0]);
      }
      #pragma unroll
      for (int mi = 0; mi < 4; mi++)
        #pragma unroll
        for (int t = 0; t < 8; t++)
          mma8(c[mi][t], a[mi], b[t]);
    }
    __syncthreads();
    if (kb + 2 < nk) issue(kb + 2, (kb + 2) % 3);
  }

  // epilogue
  #pragma unroll
  for (int ni = 0; ni < 8; ni++){
    int col = bx * 256 + wn + ni * 8 + 2 * tig;
    float bb0 = bias[col], bb1 = bias[col + 1];
    #pragma unroll
    for (int mi = 0; mi < 4; mi++){
      int row0 = by * 128 + wm + mi * 16 + gid;
      float2 v0, v1;
      v0.x = c[mi][ni][0] + bb0; v0.y = c[mi][ni][1] + bb1;
      v1.x = c[mi][ni][2] + bb0; v1.y = c[mi][ni][3] + bb1;
      if (EPI == 1){
        v0.x = gelu_exact(v0.x); v0.y = gelu_exact(v0.y);
        v1.x = gelu_exact(v1.x); v1.y = gelu_exact(v1.y);
      }
      if (EPI == 2){
        float2 r0 = *(const float2*)&res[(size_t)row0 * N + col];
        float2 r1 = *(const float2*)&res[(size_t)(row0 + 8) * N + col];
        v0.x += r0.x; v0.y += r0.y;
        v1.x += r1.x; v1.y += r1.y;
      }
      if (ROUT){
        v0.x = tf32r(v0.x); v0.y = tf32r(v0.y);
        v1.x = tf32r(v1.x); v1.y = tf32r(v1.y);
      }
      *(float2*)&C[(size_t)row0 * N + col]       = v0;
      *(float2*)&C[(size_t)(row0 + 8) * N + col] = v1;
    }
  }
}

// ---------------------------------------------------------------------------
// tf32 mma.sync flash attention (as R5).
// ---------------------------------------------------------------------------
#define AT_TILE_F  8448
#define AT_BUF_F   16896
#define AT_PS_F    33792
#define AT_SMEM    ((AT_PS_F + 128 * 68) * 4)

__global__ __launch_bounds__(256, 1) void attn_mma_kernel(
    const float* __restrict__ qkv, float* __restrict__ av)
{
  extern __shared__ float sm[];
  float* Ps = sm + AT_PS_F;
  uint32_t sbase = s2u(sm);

  int qt = blockIdx.x, bh = blockIdx.y;
  int b = bh >> 4, h = bh & 15;
  int q0 = qt * 128;
  int tid = threadIdx.x, warp = tid >> 5, lane = tid & 31;
  int gid = lane >> 2, tig = lane & 3;
  int wq = warp * 16;
  const float scl = 0.08838834764831845f;

  const float* base = qkv + (size_t)(b * SEQ) * (3 * DMODEL) + h * 128;

  int r0 = q0 + wq + gid;
  const float* Qp0 = base + (size_t)r0 * (3 * DMODEL);
  const float* Qp1 = Qp0 + (size_t)8 * (3 * DMODEL);
  uint32_t qa[16][4];
  #pragma unroll
  for (int ks = 0; ks < 16; ks++){
    qa[ks][0] = __float_as_uint(__ldg(Qp0 + 8 * ks + tig));
    qa[ks][1] = __float_as_uint(__ldg(Qp1 + 8 * ks + tig));
    qa[ks][2] = __float_as_uint(__ldg(Qp0 + 8 * ks + tig + 4));
    qa[ks][3] = __float_as_uint(__ldg(Qp1 + 8 * ks + tig + 4));
  }

  float O[16][4];
  #pragma unroll
  for (int u = 0; u < 16; u++)
    #pragma unroll
    for (int q = 0; q < 4; q++) O[u][q] = 0.f;
  float m0 = -1e30f, m1 = -1e30f, l0 = 0.f, l1 = 0.f;

  int ntiles = 2 * qt + 2;
  int pf_r  = tid >> 5;
  int pf_d4 = (tid & 31) * 4;
  {
    const float* kg = base + DMODEL + (size_t)pf_r * (3 * DMODEL) + pf_d4;
    #pragma unroll
    for (int it = 0; it < 8; it++){
      uint32_t dk = sbase + ((pf_r + it * 8) * 132 + pf_d4) * 4;
      const float* src = kg + (size_t)(it * 8) * (3 * DMODEL);
      cpa16(dk, src);
      cpa16(dk + AT_TILE_F * 4, src + DMODEL);
    }
    cp_commit();
  }

  for (int kt = 0; kt < ntiles; kt++){
    int buf = kt & 1;
    if (kt + 1 < ntiles){
      int k0n = (kt + 1) * 64;
      const float* kg = base + DMODEL + (size_t)(k0n + pf_r) * (3 * DMODEL) + pf_d4;
      uint32_t db = sbase + ((buf ^ 1) * AT_BUF_F) * 4;
      #pragma unroll
      for (int it = 0; it < 8; it++){
        uint32_t dk = db + ((pf_r + it * 8) * 132 + pf_d4) * 4;
        const float* src = kg + (size_t)(it * 8) * (3 * DMODEL);
        cpa16(dk, src);
        cpa16(dk + AT_TILE_F * 4, src + DMODEL);
      }
      cp_commit();
      cp_wait1();
    } else {
      cp_wait0();
    }
    __syncthreads();

    int k0 = kt * 64;
    bool active = (k0 <= q0 + wq + 15);
    if (active){
      const float* Ks = sm + buf * AT_BUF_F;
      const float* Vs = Ks + AT_TILE_F;

      float s[8][4];
      #pragma unroll
      for (int t = 0; t < 8; t++)
        #pragma unroll
        for (int q = 0; q < 4; q++) s[t][q] = 0.f;
      #pragma unroll
      for (int ks = 0; ks < 16; ks++){
        uint32_t bf[8][2];
        #pragma unroll
        for (int t = 0; t < 8; t++){
          int n0 = 8 * t + gid;
          bf[t][0] = __float_as_uint(Ks[n0 * 132 + 8 * ks + tig]);
          bf[t][1] = __float_as_uint(Ks[n0 * 132 + 8 * ks + tig + 4]);
        }
        #pragma unroll
        for (int t = 0; t < 8; t++)
          mma8(s[t], qa[ks], bf[t]);
      }

      bool dg = (kt >= 2 * qt);
      float mx0 = -1e30f, mx1 = -1e30f;
      #pragma unroll
      for (int t = 0; t < 8; t++){
        float c0 = s[t][0] * scl, c1 = s[t][1] * scl;
        float c2 = s[t][2] * scl, c3 = s[t][3] * scl;
        if (dg){
          int g0 = k0 + 8 * t + 2 * tig;
          if (g0     > r0)     c0 = -1e30f;
          if (g0 + 1 > r0)     c1 = -1e30f;
          if (g0     > r0 + 8) c2 = -1e30f;
          if (g0 + 1 > r0 + 8) c3 = -1e30f;
        }
        s[t][0] = c0; s[t][1] = c1; s[t][2] = c2; s[t][3] = c3;
        mx0 = fmaxf(mx0, fmaxf(c0, c1));
        mx1 = fmaxf(mx1, fmaxf(c2, c3));
      }
      #pragma unroll
      for (int m = 1; m < 4; m <<= 1){
        mx0 = fmaxf(mx0, __shfl_xor_sync(0xffffffffu, mx0, m));
        mx1 = fmaxf(mx1, __shfl_xor_sync(0xffffffffu, mx1, m));
      }
      float mn0 = fmaxf(m0, mx0), mn1 = fmaxf(m1, mx1);
      float cr0 = __expf(m0 - mn0), cr1 = __expf(m1 - mn1);
      m0 = mn0; m1 = mn1;
      float ls0 = 0.f, ls1 = 0.f;
      int lr0 = wq + gid, lr1 = wq + gid + 8;
      #pragma unroll
      for (int t = 0; t < 8; t++){
        float p0 = __expf(s[t][0] - mn0);
        float p1 = __expf(s[t][1] - mn0);
        float p2 = __expf(s[t][2] - mn1);
        float p3 = __expf(s[t][3] - mn1);
        ls0 += p0 + p1; ls1 += p2 + p3;
        float2 w0 = make_float2(tf32r(p0), tf32r(p1));
        float2 w1 = make_float2(tf32r(p2), tf32r(p3));
        *(float2*)&Ps[lr0 * 68 + 8 * t + 2 * tig] = w0;
        *(float2*)&Ps[lr1 * 68 + 8 * t + 2 * tig] = w1;
      }
      #pragma unroll
      for (int m = 1; m < 4; m <<= 1){
        ls0 += __shfl_xor_sync(0xffffffffu, ls0, m);
        ls1 += __shfl_xor_sync(0xffffffffu, ls1, m);
      }
      l0 = l0 * cr0 + ls0;
      l1 = l1 * cr1 + ls1;
      #pragma unroll
      for (int u = 0; u < 16; u++){
        O[u][0] *= cr0; O[u][1] *= cr0;
        O[u][2] *= cr1; O[u][3] *= cr1;
      }
      __syncwarp();

      #pragma unroll
      for (int ks = 0; ks < 8; ks++){
        uint32_t a[4];
        a[0] = __float_as_uint(Ps[lr0 * 68 + 8 * ks + tig]);
        a[1] = __float_as_uint(Ps[lr1 * 68 + 8 * ks + tig]);
        a[2] = __float_as_uint(Ps[lr0 * 68 + 8 * ks + tig + 4]);
        a[3] = __float_as_uint(Ps[lr1 * 68 + 8 * ks + tig + 4]);
        #pragma unroll
        for (int u = 0; u < 16; u++){
          uint32_t bf[2];
          bf[0] = __float_as_uint(Vs[(8 * ks + tig) * 132 + 8 * u + gid]);
          bf[1] = __float_as_uint(Vs[(8 * ks + tig + 4) * 132 + 8 * u + gid]);
          mma8(O[u], a, bf);
        }
      }
      __syncwarp();
    }
    __syncthreads();
  }

  float i0 = 1.0f / l0, i1 = 1.0f / l1;
  float* o0 = av + ((size_t)(b * SEQ) + r0) * DMODEL + h * 128;
  float* o1 = o0 + (size_t)8 * DMODEL;
  #pragma unroll
  for (int u = 0; u < 16; u++){
    float2 v0 = make_float2(tf32r(O[u][0] * i0), tf32r(O[u][1] * i0));
    float2 v1 = make_float2(tf32r(O[u][2] * i1), tf32r(O[u][3] * i1));
    *(float2*)&o0[8 * u + 2 * tig] = v0;
    *(float2*)&o1[8 * u + 2 * tig] = v1;
  }
}

// ---------------- launch ----------------
extern "C" void kernel_launch(void* const* d_in, const int* in_sizes, int n_in,
                              void* d_out, int out_size)
{
  const float* x     = (const float*)d_in[0];
  const float* ln1_g = (const float*)d_in[1];
  const float* ln1_b = (const float*)d_in[2];
  const float* qkv_w = (const float*)d_in[3];
  const float* qkv_b = (const float*)d_in[4];
  const float* out_w = (const float*)d_in[5];
  const float* out_b = (const float*)d_in[6];
  const float* ln2_g = (const float*)d_in[7];
  const float* ln2_b = (const float*)d_in[8];
  const float* w1    = (const float*)d_in[9];
  const float* b1    = (const float*)d_in[10];
  const float* w2    = (const float*)d_in[11];
  const float* b2    = (const float*)d_in[12];
  float* out = (float*)d_out;

  float *h_p, *qkv_p, *av_p, *x1_p, *ffn_p, *wqkv_p, *wout_p, *w1_p, *w2_p;
  cudaGetSymbolAddress((void**)&h_p,    g_h);
  cudaGetSymbolAddress((void**)&qkv_p,  g_qkv);
  cudaGetSymbolAddress((void**)&av_p,   g_av);
  cudaGetSymbolAddress((void**)&x1_p,   g_x1);
  cudaGetSymbolAddress((void**)&ffn_p,  g_ffn);
  cudaGetSymbolAddress((void**)&wqkv_p, g_wqkv_r);
  cudaGetSymbolAddress((void**)&wout_p, g_wout_r);
  cudaGetSymbolAddress((void**)&w1_p,   g_w1_r);
  cudaGetSymbolAddress((void**)&w2_p,   g_w2_r);

  cudaFuncSetAttribute(attn_mma_kernel, cudaFuncAttributeMaxDynamicSharedMemorySize, AT_SMEM);
  cudaFuncSetAttribute(tfgemm2<0,1>, cudaFuncAttributeMaxDynamicSharedMemorySize, G2_SMEM);
  cudaFuncSetAttribute(tfgemm2<1,1>, cudaFuncAttributeMaxDynamicSharedMemorySize, G2_SMEM);
  cudaFuncSetAttribute(tfgemm2<2,0>, cudaFuncAttributeMaxDynamicSharedMemorySize, G2_SMEM);

  round_kernel<<<3 * DMODEL * DMODEL / 1024, 256>>>(qkv_w, wqkv_p);
  round_kernel<<<DMODEL * DMODEL / 1024, 256>>>(out_w, wout_p);
  round_kernel<<<DMODEL * FFDIM / 1024, 256>>>(w1, w1_p);
  round_kernel<<<FFDIM * DMODEL / 1024, 256>>>(w2, w2_p);

  // 1. LN1 -> rounded
  ln_kernel<<<NTOK, 256>>>(x, ln1_g, ln1_b, h_p);

  // 2. QKV = h @ qkv_w + b (rounded out; attention consumes tf32)
  tfgemm2<0,1><<<dim3(24, 32), 256, G2_SMEM>>>(h_p, wqkv_p, qkv_b, nullptr, qkv_p,
                                               NTOK, 3 * DMODEL, DMODEL);

  // 3. mma flash attention -> rounded
  attn_mma_kernel<<<dim3(SEQ / 128, 2 * NHEAD), 256, AT_SMEM>>>(qkv_p, av_p);

  // 4. x1 = x + av @ out_w + out_b (fp32)
  tfgemm2<2,0><<<dim3(8, 32), 256, G2_SMEM>>>(av_p, wout_p, out_b, x, x1_p,
                                              NTOK, DMODEL, DMODEL);

  // 5. LN2 -> rounded
  ln_kernel<<<NTOK, 256>>>(x1_p, ln2_g, ln2_b, h_p);

  // 6. ffn = gelu(h @ w1 + b1) -> rounded
  tfgemm2<1,1><<<dim3(32, 32), 256, G2_SMEM>>>(h_p, w1_p, b1, nullptr, ffn_p,
                                               NTOK, FFDIM, DMODEL);

  // 7. out = x1 + ffn @ w2 + b2 (fp32)
  tfgemm2<2,0><<<dim3(8, 32), 256, G2_SMEM>>>(ffn_p, w2_p, b2, x1_p, out,
                                              NTOK, DMODEL, FFDIM);
}